// round 1
// baseline (speedup 1.0000x reference)
#include <cuda_runtime.h>
#include <cstdint>

#define Bb 16
#define NN 577
#define CC 768
#define HH 12
#define HD 64
#define BH (Bb*HH)          // 192
#define MX (Bb*NN)          // 9232
#define SCALE 0.125f        // HD^-0.5

// ---- scratch (static device arrays; no runtime allocation) ----
static __device__ float g_q[(size_t)BH*NN*HD];   // (b,h,n,d), pre-scaled
static __device__ float g_k[(size_t)BH*NN*HD];
static __device__ float g_v[(size_t)BH*NN*HD];
static __device__ float g_Y[(size_t)BH*NN*HD];   // A @ v
static __device__ float g_A[(size_t)BH*NN*NN];   // logits -> softmax(A)
static __device__ float g_hb[(size_t)MX*CC];     // merged-head output (b,n,c)

// ---------------------------------------------------------------------------
// Shared 64x64x16 tile machinery. 256 threads, 4x4 micro-tile per thread.
// ---------------------------------------------------------------------------
__device__ __forceinline__ void tile_compute(
    const float (&As)[16][64], const float (&Bs)[16][64],
    float (&acc)[4][4], int tx, int ty)
{
#pragma unroll
    for (int kk = 0; kk < 16; kk++) {
        float a[4], b[4];
#pragma unroll
        for (int i = 0; i < 4; i++) a[i] = As[kk][ty*4 + i];
#pragma unroll
        for (int j = 0; j < 4; j++) b[j] = Bs[kk][tx*4 + j];
#pragma unroll
        for (int i = 0; i < 4; i++)
#pragma unroll
            for (int j = 0; j < 4; j++)
                acc[i][j] = fmaf(a[i], b[j], acc[i][j]);
    }
}

// Load a 64(row) x 16(k) tile from a row-major matrix (row stride = ld),
// rows are the "outer" dim (works for A of NT/NN, and B of NT).
__device__ __forceinline__ void load_rowmajor_rk(
    const float* __restrict__ M, int ld, int nrows, int ncols,
    int r0, int k0, float (&S)[16][64], int tid)
{
#pragma unroll
    for (int i = 0; i < 4; i++) {
        int e  = tid + i*256;
        int r  = e >> 4;        // 0..63
        int kk = e & 15;        // 0..15
        int gr = r0 + r, gc = k0 + kk;
        S[kk][r] = (gr < nrows && gc < ncols) ? M[(size_t)gr*ld + gc] : 0.f;
    }
}

// Load a 16(k) x 64(col) tile from a row-major K x Nc matrix (for NN B operand).
__device__ __forceinline__ void load_rowmajor_kc(
    const float* __restrict__ M, int ld, int K, int Nc,
    int k0, int n0, float (&S)[16][64], int tid)
{
#pragma unroll
    for (int i = 0; i < 4; i++) {
        int e  = tid + i*256;
        int kk = e >> 6;        // 0..15
        int n  = e & 63;        // 0..63
        int gk = k0 + kk, gn = n0 + n;
        S[kk][n] = (gk < K && gn < Nc) ? M[(size_t)gk*ld + gn] : 0.f;
    }
}

// ---------------------------------------------------------------------------
// K1: QKV projection. C[m,o] = sum_k x[m,k] * W[o,k]  (NT), scattered to
// (b,h,n,d) layout; q gets SCALE. grid = (12, 145, 3)
// ---------------------------------------------------------------------------
__global__ __launch_bounds__(256) void k_qkv(
    const float* __restrict__ x,
    const float* __restrict__ Wq, const float* __restrict__ Wk,
    const float* __restrict__ Wv)
{
    __shared__ float As[16][64], Bs[16][64];
    int tid = threadIdx.x, tx = tid & 15, ty = tid >> 4;
    int m0 = blockIdx.y * 64, n0 = blockIdx.x * 64;

    const float* W; float* out; float scale;
    if (blockIdx.z == 0)      { W = Wq; out = g_q; scale = SCALE; }
    else if (blockIdx.z == 1) { W = Wk; out = g_k; scale = 1.f; }
    else                      { W = Wv; out = g_v; scale = 1.f; }

    float acc[4][4] = {};
    for (int k0 = 0; k0 < CC; k0 += 16) {
        load_rowmajor_rk(x, CC, MX, CC, m0, k0, As, tid);
        load_rowmajor_rk(W, CC, CC, CC, n0, k0, Bs, tid);
        __syncthreads();
        tile_compute(As, Bs, acc, tx, ty);
        __syncthreads();
    }
#pragma unroll
    for (int i = 0; i < 4; i++) {
        int m = m0 + ty*4 + i;
        if (m >= MX) continue;
        int b = m / NN, n = m - b*NN;
#pragma unroll
        for (int j = 0; j < 4; j++) {
            int o = n0 + tx*4 + j;          // CC divisible by 64 -> always valid
            int h = o >> 6, d = o & 63;
            out[(((size_t)(b*HH + h))*NN + n)*HD + d] = acc[i][j] * scale;
        }
    }
}

// ---------------------------------------------------------------------------
// K2: logits. Per (b,h): S[i,j] = sum_d q[i,d]*k[j,d] (NT, K=64).
// grid = (10, 10, 192)
// ---------------------------------------------------------------------------
__global__ __launch_bounds__(256) void k_logits()
{
    __shared__ float As[16][64], Bs[16][64];
    int tid = threadIdx.x, tx = tid & 15, ty = tid >> 4;
    int bh = blockIdx.z;
    const float* q = g_q + (size_t)bh*NN*HD;
    const float* k = g_k + (size_t)bh*NN*HD;
    float*       S = g_A + (size_t)bh*NN*NN;
    int m0 = blockIdx.y * 64, n0 = blockIdx.x * 64;

    float acc[4][4] = {};
#pragma unroll
    for (int k0 = 0; k0 < HD; k0 += 16) {
        load_rowmajor_rk(q, HD, NN, HD, m0, k0, As, tid);
        load_rowmajor_rk(k, HD, NN, HD, n0, k0, Bs, tid);
        __syncthreads();
        tile_compute(As, Bs, acc, tx, ty);
        __syncthreads();
    }
#pragma unroll
    for (int i = 0; i < 4; i++) {
        int mi = m0 + ty*4 + i;
        if (mi >= NN) continue;
#pragma unroll
        for (int j = 0; j < 4; j++) {
            int nj = n0 + tx*4 + j;
            if (nj < NN) S[(size_t)mi*NN + nj] = acc[i][j];
        }
    }
}

// ---------------------------------------------------------------------------
// K3: row softmax over g_A. One block per row. grid = BH*NN blocks.
// ---------------------------------------------------------------------------
__global__ __launch_bounds__(256) void k_softmax()
{
    int row = blockIdx.x;
    float* p = g_A + (size_t)row * NN;
    int tid = threadIdx.x;
    __shared__ float red[8];

    float m = -1e30f;
    for (int j = tid; j < NN; j += 256) m = fmaxf(m, p[j]);
#pragma unroll
    for (int o = 16; o; o >>= 1) m = fmaxf(m, __shfl_xor_sync(~0u, m, o));
    if ((tid & 31) == 0) red[tid >> 5] = m;
    __syncthreads();
    if (tid == 0) {
        float t = red[0];
#pragma unroll
        for (int i = 1; i < 8; i++) t = fmaxf(t, red[i]);
        red[0] = t;
    }
    __syncthreads();
    m = red[0];
    __syncthreads();

    float s = 0.f;
    for (int j = tid; j < NN; j += 256) {
        float e = __expf(p[j] - m);
        p[j] = e;
        s += e;
    }
#pragma unroll
    for (int o = 16; o; o >>= 1) s += __shfl_xor_sync(~0u, s, o);
    if ((tid & 31) == 0) red[tid >> 5] = s;
    __syncthreads();
    if (tid == 0) {
        float t = 0.f;
#pragma unroll
        for (int i = 0; i < 8; i++) t += red[i];
        red[0] = t;
    }
    __syncthreads();
    float inv = 1.f / red[0];
    for (int j = tid; j < NN; j += 256) p[j] *= inv;
}

// ---------------------------------------------------------------------------
// K4: Y = A @ v per (b,h). NN form: M=577, K=577, Nc=64. grid = (1, 10, 192)
// ---------------------------------------------------------------------------
__global__ __launch_bounds__(256) void k_av()
{
    __shared__ float As[16][64], Bs[16][64];
    int tid = threadIdx.x, tx = tid & 15, ty = tid >> 4;
    int bh = blockIdx.z;
    const float* A = g_A + (size_t)bh*NN*NN;
    const float* V = g_v + (size_t)bh*NN*HD;
    float*       Y = g_Y + (size_t)bh*NN*HD;
    int m0 = blockIdx.y * 64;

    float acc[4][4] = {};
    for (int k0 = 0; k0 < NN; k0 += 16) {
        load_rowmajor_rk(A, NN, NN, NN, m0, k0, As, tid);
        load_rowmajor_kc(V, HD, NN, HD, k0, 0, Bs, tid);
        __syncthreads();
        tile_compute(As, Bs, acc, tx, ty);
        __syncthreads();
    }
#pragma unroll
    for (int i = 0; i < 4; i++) {
        int mi = m0 + ty*4 + i;
        if (mi >= NN) continue;
#pragma unroll
        for (int j = 0; j < 4; j++) {
            int o = tx*4 + j;   // < 64 always
            Y[(size_t)mi*HD + o] = acc[i][j];
        }
    }
}

// ---------------------------------------------------------------------------
// K5: Z = A @ Y; out = (1-2b)*Y + 3b*Z, scattered into (b,n,c) merged-head
// layout. grid = (1, 10, 192)
// ---------------------------------------------------------------------------
__global__ __launch_bounds__(256) void k_ay(const float* __restrict__ lamb)
{
    __shared__ float As[16][64], Bs[16][64];
    int tid = threadIdx.x, tx = tid & 15, ty = tid >> 4;
    int bh = blockIdx.z;
    int b = bh / HH, h = bh - b*HH;
    const float* A = g_A + (size_t)bh*NN*NN;
    const float* Y = g_Y + (size_t)bh*NN*HD;
    int m0 = blockIdx.y * 64;

    float beta = lamb[h];
    float c0 = 1.f - 2.f*beta;
    float c1 = 3.f*beta;

    float acc[4][4] = {};
    for (int k0 = 0; k0 < NN; k0 += 16) {
        load_rowmajor_rk(A, NN, NN, NN, m0, k0, As, tid);
        load_rowmajor_kc(Y, HD, NN, HD, k0, 0, Bs, tid);
        __syncthreads();
        tile_compute(As, Bs, acc, tx, ty);
        __syncthreads();
    }
#pragma unroll
    for (int i = 0; i < 4; i++) {
        int mi = m0 + ty*4 + i;
        if (mi >= NN) continue;
#pragma unroll
        for (int j = 0; j < 4; j++) {
            int o = tx*4 + j;
            float y = Y[(size_t)mi*HD + o];
            g_hb[((size_t)b*NN + mi)*CC + h*HD + o] = c0*y + c1*acc[i][j];
        }
    }
}

// ---------------------------------------------------------------------------
// K6: out = g_hb @ Wp^T + bp. NT: M=9232, Nc=768, K=768. grid = (12, 145)
// ---------------------------------------------------------------------------
__global__ __launch_bounds__(256) void k_proj(
    const float* __restrict__ Wp, const float* __restrict__ bp,
    float* __restrict__ out)
{
    __shared__ float As[16][64], Bs[16][64];
    int tid = threadIdx.x, tx = tid & 15, ty = tid >> 4;
    int m0 = blockIdx.y * 64, n0 = blockIdx.x * 64;

    float acc[4][4] = {};
    for (int k0 = 0; k0 < CC; k0 += 16) {
        load_rowmajor_rk(g_hb, CC, MX, CC, m0, k0, As, tid);
        load_rowmajor_rk(Wp,   CC, CC, CC, n0, k0, Bs, tid);
        __syncthreads();
        tile_compute(As, Bs, acc, tx, ty);
        __syncthreads();
    }
#pragma unroll
    for (int i = 0; i < 4; i++) {
        int m = m0 + ty*4 + i;
        if (m >= MX) continue;
#pragma unroll
        for (int j = 0; j < 4; j++) {
            int o = n0 + tx*4 + j;
            out[(size_t)m*CC + o] = acc[i][j] + bp[o];
        }
    }
}

// ---------------------------------------------------------------------------
extern "C" void kernel_launch(void* const* d_in, const int* in_sizes, int n_in,
                              void* d_out, int out_size)
{
    const float* x    = (const float*)d_in[0];
    const float* Wq   = (const float*)d_in[1];
    const float* Wk   = (const float*)d_in[2];
    const float* Wv   = (const float*)d_in[3];
    const float* Wp   = (const float*)d_in[4];
    const float* bp   = (const float*)d_in[5];
    const float* lamb = (const float*)d_in[6];
    float* out = (float*)d_out;

    dim3 blk(256);
    k_qkv   <<<dim3(CC/64, (MX+63)/64, 3), blk>>>(x, Wq, Wk, Wv);
    k_logits<<<dim3((NN+63)/64, (NN+63)/64, BH), blk>>>();
    k_softmax<<<BH*NN, 256>>>();
    k_av    <<<dim3(1, (NN+63)/64, BH), blk>>>();
    k_ay    <<<dim3(1, (NN+63)/64, BH), blk>>>(lamb);
    k_proj  <<<dim3(CC/64, (MX+63)/64, 1), blk>>>(Wp, bp, out);
}

// round 3
// speedup vs baseline: 3.9773x; 3.9773x over previous
#include <cuda_runtime.h>
#include <cstdint>

#define Bb 16
#define NN 577
#define NP 640              // padded token dim
#define CC 768
#define HH 12
#define HD 64
#define BH (Bb*HH)          // 192
#define MX (Bb*NN)          // 9232
#define SCALE 0.125f

// ---- scratch (static device arrays; zero-initialized; pads stay zero) ----
static __device__ float g_q [(size_t)BH*NP*HD];   // [bh][n(pad)][d], q pre-scaled
static __device__ float g_k [(size_t)BH*NP*HD];
static __device__ float g_vt[(size_t)BH*HD*NP];   // V^T : [bh][d][n(pad)]
static __device__ float g_Yt[(size_t)BH*HD*NP];   // (A@v)^T
static __device__ float g_A [(size_t)BH*NP*NP];   // logits -> softmax(A), pads zeroed
static __device__ float g_hb[(size_t)MX*CC];      // merged-head (b,n,c)

// ======================== low-level helpers (base sm_80+ PTX only) ========
__device__ __forceinline__ void cpa16(uint32_t dst, const void* src){
    asm volatile("cp.async.cg.shared.global [%0], [%1], 16;\n" :: "r"(dst), "l"(src));
}
#define CP_COMMIT() asm volatile("cp.async.commit_group;\n" ::)
#define CP_WAIT(n)  asm volatile("cp.async.wait_group %0;\n" :: "n"(n))

__device__ __forceinline__ uint32_t f2tf(float f){
    uint32_t u; asm("cvt.rna.tf32.f32 %0, %1;" : "=r"(u) : "f"(f)); return u;
}
__device__ __forceinline__ float lds(uint32_t a){
    float f; asm volatile("ld.shared.f32 %0, [%1];" : "=f"(f) : "r"(a)); return f;
}
__device__ __forceinline__ void mma8(float* c, const uint32_t* a, const uint32_t* b){
    asm volatile("mma.sync.aligned.m16n8k8.row.col.f32.tf32.tf32.f32 "
        "{%0,%1,%2,%3}, {%4,%5,%6,%7}, {%8,%9}, {%0,%1,%2,%3};"
        : "+f"(c[0]), "+f"(c[1]), "+f"(c[2]), "+f"(c[3])
        : "r"(a[0]), "r"(a[1]), "r"(a[2]), "r"(a[3]), "r"(b[0]), "r"(b[1]));
}

// ======================== tiled NT tf32 GEMM mainloop =====================
// D[128 x BN] = A[128 rows x K] * B[BN rows x K]^T, both K-major (NT).
// 256 threads, 8 warps: warp_m = wid>>1 (32 rows), warp_n = wid&1 (BN/2 cols).
// SMEM layout per buffer: [row][K=16 + 4 pad] fp32 -> 80 B/row.
#define ABUF 10240          // 128*20*4

template<int BN>
__device__ __forceinline__ void gemm_nt(
    const float* __restrict__ A, int ldA, int a_r0, int a_clamp,
    const float* __restrict__ B, int ldB, int b_r0,
    int Ktot, char* sm, float (&acc)[2][BN/16][4], int tid)
{
    constexpr int NT   = BN/16;
    constexpr int BBUF = BN*80;
    const int wid = tid >> 5, lane = tid & 31;
    const int wm = wid >> 1, wn = wid & 1;
    const int g = lane >> 2, t = lane & 3;
    uint32_t sA = (uint32_t)__cvta_generic_to_shared(sm);
    uint32_t sB = sA + 2*ABUF;
    const int T = Ktot / 16;

    auto load_tiles = [&](int kt, int buf){
        int k0 = kt * 16;
#pragma unroll
        for (int i = 0; i < 2; i++){
            int e = tid + i*256;
            int r = e >> 2, c4 = e & 3;
            int gr = a_r0 + r;
            if (a_clamp) gr = (gr < a_clamp) ? gr : (a_clamp - 1);
            cpa16(sA + buf*ABUF + r*80 + c4*16, A + (size_t)gr*ldA + k0 + c4*4);
        }
#pragma unroll
        for (int i = 0; i < BN*4/256; i++){
            int e = tid + i*256;
            int r = e >> 2, c4 = e & 3;
            cpa16(sB + buf*BBUF + r*80 + c4*16, B + (size_t)(b_r0 + r)*ldB + k0 + c4*4);
        }
        CP_COMMIT();
    };

    load_tiles(0, 0);
    for (int kt = 0; kt < T; kt++){
        if (kt + 1 < T){ load_tiles(kt + 1, (kt + 1) & 1); CP_WAIT(1); }
        else           { CP_WAIT(0); }
        __syncthreads();
        uint32_t aB = sA + (kt & 1)*ABUF, bB = sB + (kt & 1)*BBUF;
#pragma unroll
        for (int ks = 0; ks < 2; ks++){
            uint32_t afr[2][4], bfr[NT][2];
#pragma unroll
            for (int mt = 0; mt < 2; mt++){
                uint32_t base = aB + ((wm*32 + mt*16 + g)*20 + ks*8 + t)*4;
                afr[mt][0] = f2tf(lds(base));
                afr[mt][1] = f2tf(lds(base + 8*80));
                afr[mt][2] = f2tf(lds(base + 16));
                afr[mt][3] = f2tf(lds(base + 8*80 + 16));
            }
#pragma unroll
            for (int nt = 0; nt < NT; nt++){
                uint32_t base = bB + ((wn*(BN/2) + nt*8 + g)*20 + ks*8 + t)*4;
                bfr[nt][0] = f2tf(lds(base));
                bfr[nt][1] = f2tf(lds(base + 16));
            }
#pragma unroll
            for (int mt = 0; mt < 2; mt++)
#pragma unroll
                for (int nt = 0; nt < NT; nt++)
                    mma8(acc[mt][nt], afr[mt], bfr[nt]);
        }
        __syncthreads();
    }
}

// C-fragment coordinates: row = wm*32 + mt*16 + g + (c>>1)*8
//                         col = wn*(BN/2) + nt*8 + t*2 + (c&1)
#define EPI_LOOP(BN) \
    for (int mt = 0; mt < 2; mt++) for (int nt = 0; nt < BN/16; nt++) \
        for (int c = 0; c < 4; c++)
#define EPI_ROW (wm*32 + mt*16 + g + (c>>1)*8)
#define EPI_COL (wn*((BN_)/2) + nt*8 + t*2 + (c&1))

// ======================== kernels ========================
// K1: QKV projection (NT). grid (6, 73, 3)
__global__ void __launch_bounds__(256)
k_qkv(const float* __restrict__ x, const float* __restrict__ Wq,
      const float* __restrict__ Wk, const float* __restrict__ Wv){
    constexpr int BN_ = 128;
    __shared__ __align__(16) char sm[4*ABUF];
    int tid = threadIdx.x;
    int wid = tid >> 5, lane = tid & 31;
    int wm = wid >> 1, wn = wid & 1, g = lane >> 2, t = lane & 3;
    int z = blockIdx.z, m0 = blockIdx.y * 128, n0 = blockIdx.x * 128;
    const float* W = (z == 0) ? Wq : (z == 1) ? Wk : Wv;

    float acc[2][8][4] = {};
    gemm_nt<128>(x, CC, m0, MX, W, CC, n0, CC, sm, acc, tid);

    float scale = (z == 0) ? SCALE : 1.f;
    EPI_LOOP(128){
        int gm = m0 + EPI_ROW;
        if (gm >= MX) continue;
        int b = gm / NN, n = gm - b*NN;
        int o = n0 + EPI_COL, h = o >> 6, d = o & 63;
        float v = acc[mt][nt][c] * scale;
        if (z == 0)      g_q [(((size_t)(b*HH + h))*NP + n)*HD + d] = v;
        else if (z == 1) g_k [(((size_t)(b*HH + h))*NP + n)*HD + d] = v;
        else             g_vt[(((size_t)(b*HH + h))*HD + d)*NP + n] = v;
    }
}

// K2: logits (NT, K=64) with coalesced smem-staged store. grid (5, 5, 192)
__global__ void __launch_bounds__(256)
k_logits(){
    constexpr int BN_ = 128;
    __shared__ __align__(16) char sm[4*ABUF];
    int tid = threadIdx.x;
    int wid = tid >> 5, lane = tid & 31;
    int wm = wid >> 1, wn = wid & 1, g = lane >> 2, t = lane & 3;
    int bh = blockIdx.z, m0 = blockIdx.y * 128, n0 = blockIdx.x * 128;
    const float* q = g_q + (size_t)bh * NP * HD;
    const float* k = g_k + (size_t)bh * NP * HD;
    float* S = g_A + (size_t)bh * NP * NP;

    float acc[2][8][4] = {};
    gemm_nt<128>(q, HD, m0, 0, k, HD, n0, HD, sm, acc, tid);

    float* stg = (float*)sm;                 // 128 x 68 staging (34.8 KB)
    for (int half = 0; half < 2; half++){
        __syncthreads();
        if (wn == half){
            EPI_LOOP(128){
                int lc = nt*8 + t*2 + (c&1);  // 0..63 local col
                stg[EPI_ROW * 68 + lc] = acc[mt][nt][c];
            }
        }
        __syncthreads();
#pragma unroll
        for (int i = 0; i < 8; i++){
            int e = tid + i*256;
            int r = e >> 4, c4 = e & 15;
            float4 v = *(const float4*)&stg[r*68 + c4*4];
            *(float4*)&S[(size_t)(m0 + r)*NP + n0 + half*64 + c4*4] = v;
        }
    }
}

// K3: row softmax over g_A (valid 577 cols; zero pads). grid 192*640.
__global__ void __launch_bounds__(256) k_softmax(){
    int row = blockIdx.x;
    int i = row % NP;
    float* p = g_A + (size_t)row * NP;
    int tid = threadIdx.x;
    if (i >= NN){
        for (int j = tid; j < NP; j += 256) p[j] = 0.f;
        return;
    }
    __shared__ float red[8];
    float m = -1e30f;
    for (int j = tid; j < NN; j += 256) m = fmaxf(m, p[j]);
#pragma unroll
    for (int o = 16; o; o >>= 1) m = fmaxf(m, __shfl_xor_sync(~0u, m, o));
    if ((tid & 31) == 0) red[tid >> 5] = m;
    __syncthreads();
    if (tid == 0){ float v = red[0];
#pragma unroll
        for (int q = 1; q < 8; q++) v = fmaxf(v, red[q]); red[0] = v; }
    __syncthreads();
    m = red[0]; __syncthreads();
    float s = 0.f;
    for (int j = tid; j < NN; j += 256){ float e = __expf(p[j] - m); p[j] = e; s += e; }
#pragma unroll
    for (int o = 16; o; o >>= 1) s += __shfl_xor_sync(~0u, s, o);
    if ((tid & 31) == 0) red[tid >> 5] = s;
    __syncthreads();
    if (tid == 0){ float v = 0.f;
#pragma unroll
        for (int q = 0; q < 8; q++) v += red[q]; red[0] = v; }
    __syncthreads();
    float inv = 1.f / red[0];
    for (int j = tid; j < NN; j += 256) p[j] *= inv;
    for (int j = NN + tid; j < NP; j += 256) p[j] = 0.f;
}

// K4: Y^T = (A @ v)^T. grid (1, 5, 192). BN=64.
__global__ void __launch_bounds__(256)
k_av(){
    constexpr int BN_ = 64;
    __shared__ __align__(16) char sm[2*ABUF + 2*64*80];
    int tid = threadIdx.x;
    int wid = tid >> 5, lane = tid & 31;
    int wm = wid >> 1, wn = wid & 1, g = lane >> 2, t = lane & 3;
    int bh = blockIdx.z, m0 = blockIdx.y * 128;
    const float* A  = g_A  + (size_t)bh * NP * NP;
    const float* Vt = g_vt + (size_t)bh * HD * NP;
    float* Yt = g_Yt + (size_t)bh * HD * NP;

    float acc[2][4][4] = {};
    gemm_nt<64>(A, NP, m0, 0, Vt, NP, 0, NP, sm, acc, tid);

    EPI_LOOP(64){
        int token = m0 + EPI_ROW;
        int d = EPI_COL;
        Yt[(size_t)d * NP + token] = acc[mt][nt][c];
    }
}

// K5: Z = A@Y; out = (1-2b)Y + 3b*Z -> merged (b,n,c). grid (1, 5, 192). BN=64.
__global__ void __launch_bounds__(256)
k_ay(const float* __restrict__ lamb){
    constexpr int BN_ = 64;
    __shared__ __align__(16) char sm[2*ABUF + 2*64*80];
    int tid = threadIdx.x;
    int wid = tid >> 5, lane = tid & 31;
    int wm = wid >> 1, wn = wid & 1, g = lane >> 2, t = lane & 3;
    int bh = blockIdx.z, m0 = blockIdx.y * 128;
    int b = bh / HH, h = bh - b*HH;
    const float* A  = g_A  + (size_t)bh * NP * NP;
    const float* Yt = g_Yt + (size_t)bh * HD * NP;
    float beta = lamb[h];
    float c0 = 1.f - 2.f*beta, c1 = 3.f*beta;

    float acc[2][4][4] = {};
    gemm_nt<64>(A, NP, m0, 0, Yt, NP, 0, NP, sm, acc, tid);

    EPI_LOOP(64){
        int token = m0 + EPI_ROW;
        if (token >= NN) continue;
        int d = EPI_COL;
        float y = Yt[(size_t)d * NP + token];
        g_hb[((size_t)(b*NN + token))*CC + h*HD + d] = c0*y + c1*acc[mt][nt][c];
    }
}

// K6: out = g_hb @ Wp^T + bp (NT). grid (6, 73)
__global__ void __launch_bounds__(256)
k_proj(const float* __restrict__ Wp, const float* __restrict__ bp,
       float* __restrict__ out){
    constexpr int BN_ = 128;
    __shared__ __align__(16) char sm[4*ABUF];
    int tid = threadIdx.x;
    int wid = tid >> 5, lane = tid & 31;
    int wm = wid >> 1, wn = wid & 1, g = lane >> 2, t = lane & 3;
    int m0 = blockIdx.y * 128, n0 = blockIdx.x * 128;

    float acc[2][8][4] = {};
    gemm_nt<128>(g_hb, CC, m0, MX, Wp, CC, n0, CC, sm, acc, tid);

    EPI_LOOP(128){
        int gm = m0 + EPI_ROW;
        if (gm >= MX) continue;
        int o = n0 + EPI_COL;
        out[(size_t)gm*CC + o] = acc[mt][nt][c] + bp[o];
    }
}

// ======================== host launcher ========================
extern "C" void kernel_launch(void* const* d_in, const int* in_sizes, int n_in,
                              void* d_out, int out_size)
{
    const float* x    = (const float*)d_in[0];
    const float* Wq   = (const float*)d_in[1];
    const float* Wk   = (const float*)d_in[2];
    const float* Wv   = (const float*)d_in[3];
    const float* Wp   = (const float*)d_in[4];
    const float* bp   = (const float*)d_in[5];
    const float* lamb = (const float*)d_in[6];
    float* out = (float*)d_out;

    k_qkv    <<<dim3(CC/128, (MX + 127)/128, 3), 256>>>(x, Wq, Wk, Wv);
    k_logits <<<dim3(NP/128, NP/128, BH),        256>>>();
    k_softmax<<<BH * NP, 256>>>();
    k_av     <<<dim3(1, NP/128, BH),             256>>>();
    k_ay     <<<dim3(1, NP/128, BH),             256>>>(lamb);
    k_proj   <<<dim3(CC/128, (MX + 127)/128, 1), 256>>>(Wp, bp, out);
}

// round 5
// speedup vs baseline: 9.5575x; 2.4030x over previous
#include <cuda_runtime.h>
#include <cuda_fp16.h>
#include <cstdint>

#define Bb 16
#define NN 577
#define NP 640
#define CC 768
#define HH 12
#define HD 64
#define BH (Bb*HH)          // 192
#define MX (Bb*NN)          // 9232
#define SCALE 0.125f

// ---- fp16/fp32 scratch (static device arrays; pads stay zero) ----
static __device__ __half g_xh[(size_t)MX*CC];
static __device__ __half g_wq[(size_t)CC*CC];
static __device__ __half g_wk[(size_t)CC*CC];
static __device__ __half g_wv[(size_t)CC*CC];
static __device__ __half g_wp[(size_t)CC*CC];
static __device__ __half g_q [(size_t)BH*NP*HD];   // [bh][tok][d], q pre-scaled
static __device__ __half g_k [(size_t)BH*NP*HD];
static __device__ __half g_v [(size_t)BH*NP*HD];
static __device__ __half g_Yh[(size_t)BH*NP*HD];   // A@v fp16 [bh][tok][d]
static __device__ float  g_Yf[(size_t)BH*NP*HD];   // A@v fp32 (for epilogue)
static __device__ __half g_hb[(size_t)MX*CC];      // merged-head (b,n,c)

// ======================== low-level helpers (sm_80+ PTX) ========================
__device__ __forceinline__ uint32_t sptr(const void* p){
    return (uint32_t)__cvta_generic_to_shared(p);
}
__device__ __forceinline__ void cpa16(uint32_t dst, const void* src){
    asm volatile("cp.async.cg.shared.global [%0], [%1], 16;\n" :: "r"(dst), "l"(src));
}
#define CP_COMMIT() asm volatile("cp.async.commit_group;\n" ::)
#define CP_WAIT0()  asm volatile("cp.async.wait_group 0;\n" ::)
#define CP_WAIT1()  asm volatile("cp.async.wait_group 1;\n" ::)

__device__ __forceinline__ void ldm4(uint32_t& r0, uint32_t& r1, uint32_t& r2, uint32_t& r3, uint32_t a){
    asm volatile("ldmatrix.sync.aligned.m8n8.x4.shared.b16 {%0,%1,%2,%3}, [%4];"
        : "=r"(r0), "=r"(r1), "=r"(r2), "=r"(r3) : "r"(a));
}
__device__ __forceinline__ void ldm4t(uint32_t& r0, uint32_t& r1, uint32_t& r2, uint32_t& r3, uint32_t a){
    asm volatile("ldmatrix.sync.aligned.m8n8.x4.trans.shared.b16 {%0,%1,%2,%3}, [%4];"
        : "=r"(r0), "=r"(r1), "=r"(r2), "=r"(r3) : "r"(a));
}
__device__ __forceinline__ void mma16(float* c, const uint32_t* a, const uint32_t* b){
    asm volatile("mma.sync.aligned.m16n8k16.row.col.f32.f16.f16.f32 "
        "{%0,%1,%2,%3}, {%4,%5,%6,%7}, {%8,%9}, {%0,%1,%2,%3};"
        : "+f"(c[0]), "+f"(c[1]), "+f"(c[2]), "+f"(c[3])
        : "r"(a[0]), "r"(a[1]), "r"(a[2]), "r"(a[3]), "r"(b[0]), "r"(b[1]));
}
__device__ __forceinline__ uint32_t packh2(float lo, float hi){
    __half2 h = __floats2half2_rn(lo, hi);
    return *reinterpret_cast<uint32_t*>(&h);
}

// ======================== fp16 NT GEMM mainloop (128x128, BK=32) ===============
// D[128 x 128] = A[128 x K] * B[128 x K]^T. 256 threads, 8 warps (4m x 2n).
// SMEM rows: 32 halves + 8 pad = 40 halves (80B) -> conflict-free ldmatrix.
#define GBUF (128*40)   // halves per buffer

__device__ __forceinline__ void gemm_nt_h(
    const __half* __restrict__ A, int ldA, int a_r0, int a_clamp,
    const __half* __restrict__ B, int ldB, int b_r0,
    int Ktot, __half* sm, float (&acc)[2][8][4], int tid)
{
    const int lane = tid & 31, wid = tid >> 5;
    const int wm = wid >> 1, wn = wid & 1;
    uint32_t sA = sptr(sm), sB = sptr(sm + 2*GBUF);
    const int T = Ktot / 32;

    auto load = [&](int kt, int buf){
        int k0 = kt*32;
#pragma unroll
        for (int i = 0; i < 2; i++){
            int e = tid + i*256;
            int r = e >> 2, c = e & 3;
            int gr = a_r0 + r; if (a_clamp) gr = (gr < a_clamp) ? gr : (a_clamp - 1);
            cpa16(sA + (buf*GBUF + r*40)*2 + c*16, A + (size_t)gr*ldA + k0 + c*8);
        }
#pragma unroll
        for (int i = 0; i < 2; i++){
            int e = tid + i*256;
            int r = e >> 2, c = e & 3;
            cpa16(sB + (buf*GBUF + r*40)*2 + c*16, B + (size_t)(b_r0 + r)*ldB + k0 + c*8);
        }
        CP_COMMIT();
    };

    load(0, 0);
    for (int kt = 0; kt < T; kt++){
        if (kt + 1 < T){ load(kt + 1, (kt + 1) & 1); CP_WAIT1(); }
        else           { CP_WAIT0(); }
        __syncthreads();
        uint32_t aB = sA + ((kt & 1)*GBUF)*2;
        uint32_t bB = sB + ((kt & 1)*GBUF)*2;
#pragma unroll
        for (int kf = 0; kf < 2; kf++){
            uint32_t af[2][4], bf[8][2];
#pragma unroll
            for (int mt = 0; mt < 2; mt++){
                uint32_t a = aB + ((wm*32 + mt*16 + (lane & 15))*40 + kf*16 + (lane >> 4)*8)*2;
                ldm4(af[mt][0], af[mt][1], af[mt][2], af[mt][3], a);
            }
#pragma unroll
            for (int p = 0; p < 4; p++){
                uint32_t a = bB + ((wn*64 + p*16 + (lane & 7) + ((lane >> 4) & 1)*8)*40
                                   + kf*16 + ((lane >> 3) & 1)*8)*2;
                ldm4(bf[2*p][0], bf[2*p][1], bf[2*p+1][0], bf[2*p+1][1], a);
            }
#pragma unroll
            for (int mt = 0; mt < 2; mt++)
#pragma unroll
                for (int nf = 0; nf < 8; nf++)
                    mma16(acc[mt][nf], af[mt], bf[nf]);
        }
        __syncthreads();
    }
}

// ======================== kernels ========================
// K0: fp32 -> fp16 conversion
__global__ void __launch_bounds__(256) k_cvt(const float* __restrict__ s, int sel, int n8){
    int i = blockIdx.x*256 + threadIdx.x;
    if (i >= n8) return;
    __half* d = (sel == 0) ? g_xh : (sel == 1) ? g_wq : (sel == 2) ? g_wk
              : (sel == 3) ? g_wv : g_wp;
    const float4* s4 = (const float4*)s;
    float4 a = s4[2*i], b = s4[2*i+1];
    uint4 o;
    o.x = packh2(a.x, a.y); o.y = packh2(a.z, a.w);
    o.z = packh2(b.x, b.y); o.w = packh2(b.z, b.w);
    ((uint4*)d)[i] = o;
}

// K1: QKV projection (NT), outputs [bh][tok][d] fp16. grid (6, 73, 3)
__global__ void __launch_bounds__(256) k_qkv(){
    __shared__ __align__(16) __half sm[4*GBUF];
    int tid = threadIdx.x, lane = tid & 31, wid = tid >> 5;
    int wm = wid >> 1, wn = wid & 1, g = lane >> 2, t = lane & 3;
    int z = blockIdx.z, m0 = blockIdx.y*128, n0 = blockIdx.x*128;
    const __half* W = (z == 0) ? g_wq : (z == 1) ? g_wk : g_wv;
    __half* dst = (z == 0) ? g_q : (z == 1) ? g_k : g_v;
    float scale = (z == 0) ? SCALE : 1.f;

    float acc[2][8][4] = {};
    gemm_nt_h(g_xh, CC, m0, MX, W, CC, n0, CC, sm, acc, tid);

#pragma unroll
    for (int mt = 0; mt < 2; mt++)
#pragma unroll
    for (int nf = 0; nf < 8; nf++){
        int col = n0 + wn*64 + nf*8 + t*2;
        int h = col >> 6, d = col & 63;
        int row0 = m0 + wm*32 + mt*16 + g;
#pragma unroll
        for (int rr = 0; rr < 2; rr++){
            int gm = row0 + rr*8;
            if (gm >= MX) continue;
            int b = gm / NN, n = gm - b*NN;
            uint32_t h2 = packh2(acc[mt][nf][rr*2]*scale, acc[mt][nf][rr*2+1]*scale);
            *(uint32_t*)&dst[(((size_t)(b*HH + h))*NP + n)*HD + d] = h2;
        }
    }
}

// ======================== flash attention core ========================
// Block: 128 q-rows of one (b,h). 8 warps x 16 rows. Key tiles of 64.
#define QS 72      // tile row stride in halves (144B, conflict-free)
#define OQ 0
#define OK1 (128*QS)
#define OV (128*QS + 64*QS)
#define FL_SMEM (128*QS + 2*64*QS)   // 18432 halves = 36864 B

__device__ __forceinline__ void flash_core(
    __half* smh, const __half* qg, const __half* kg, const __half* vg,
    int m0, int tid)
{
    const int lane = tid & 31, wid = tid >> 5;
    const int g = lane >> 2, t = lane & 3;
    const int wr = wid*16;
    uint32_t sq = sptr(smh + OQ), sk = sptr(smh + OK1), sv = sptr(smh + OV);

    // q tile: 128 rows x 64 halves
#pragma unroll
    for (int i = 0; i < 4; i++){
        int e = tid + i*256;
        int r = e >> 3, c = e & 7;
        cpa16(sq + (r*QS)*2 + c*16, qg + (size_t)(m0 + r)*HD + c*8);
    }
    CP_COMMIT(); CP_WAIT0();
    __syncthreads();

    uint32_t qf[4][4];
#pragma unroll
    for (int kf = 0; kf < 4; kf++){
        uint32_t a = sq + ((wr + (lane & 15))*QS + kf*16 + (lane >> 4)*8)*2;
        ldm4(qf[kf][0], qf[kf][1], qf[kf][2], qf[kf][3], a);
    }

    float mr0 = -1e30f, mr1 = -1e30f, l0 = 0.f, l1 = 0.f;
    float ya[8][4];
#pragma unroll
    for (int nf = 0; nf < 8; nf++){ ya[nf][0]=0; ya[nf][1]=0; ya[nf][2]=0; ya[nf][3]=0; }

    for (int kt = 0; kt < NP/64; kt++){
        int tok0 = kt*64;
#pragma unroll
        for (int i = 0; i < 2; i++){
            int e = tid + i*256;
            int r = e >> 3, c = e & 7;
            cpa16(sk + (r*QS)*2 + c*16, kg + (size_t)(tok0 + r)*HD + c*8);
            cpa16(sv + (r*QS)*2 + c*16, vg + (size_t)(tok0 + r)*HD + c*8);
        }
        CP_COMMIT(); CP_WAIT0();
        __syncthreads();

        // S = q @ k^T (K=64)
        float sa[8][4];
#pragma unroll
        for (int nf = 0; nf < 8; nf++){ sa[nf][0]=0; sa[nf][1]=0; sa[nf][2]=0; sa[nf][3]=0; }
#pragma unroll
        for (int kf = 0; kf < 4; kf++){
            uint32_t bf[8][2];
#pragma unroll
            for (int p = 0; p < 4; p++){
                uint32_t a = sk + ((p*16 + (lane & 7) + ((lane >> 4) & 1)*8)*QS
                                   + kf*16 + ((lane >> 3) & 1)*8)*2;
                ldm4(bf[2*p][0], bf[2*p][1], bf[2*p+1][0], bf[2*p+1][1], a);
            }
#pragma unroll
            for (int nf = 0; nf < 8; nf++) mma16(sa[nf], qf[kf], bf[nf]);
        }

        // mask invalid keys (only last tile)
        if (tok0 + 64 > NN){
#pragma unroll
            for (int nf = 0; nf < 8; nf++){
                int kb = tok0 + nf*8 + t*2;
                if (kb >= NN)     { sa[nf][0] = -1e30f; sa[nf][2] = -1e30f; }
                if (kb + 1 >= NN) { sa[nf][1] = -1e30f; sa[nf][3] = -1e30f; }
            }
        }
        // online softmax (rows fully within warp; reduce over quad lanes)
        float tm0 = -1e30f, tm1 = -1e30f;
#pragma unroll
        for (int nf = 0; nf < 8; nf++){
            tm0 = fmaxf(tm0, fmaxf(sa[nf][0], sa[nf][1]));
            tm1 = fmaxf(tm1, fmaxf(sa[nf][2], sa[nf][3]));
        }
        tm0 = fmaxf(tm0, __shfl_xor_sync(~0u, tm0, 1));
        tm0 = fmaxf(tm0, __shfl_xor_sync(~0u, tm0, 2));
        tm1 = fmaxf(tm1, __shfl_xor_sync(~0u, tm1, 1));
        tm1 = fmaxf(tm1, __shfl_xor_sync(~0u, tm1, 2));
        float mn0 = fmaxf(mr0, tm0), mn1 = fmaxf(mr1, tm1);
        float sc0 = __expf(mr0 - mn0), sc1 = __expf(mr1 - mn1);
        mr0 = mn0; mr1 = mn1;
        l0 *= sc0; l1 *= sc1;
#pragma unroll
        for (int nf = 0; nf < 8; nf++){
            ya[nf][0] *= sc0; ya[nf][1] *= sc0; ya[nf][2] *= sc1; ya[nf][3] *= sc1;
        }
        float rs0 = 0.f, rs1 = 0.f;
        uint32_t pf[4][4];
#pragma unroll
        for (int j = 0; j < 4; j++){
            float p00 = __expf(sa[2*j][0] - mr0),   p01 = __expf(sa[2*j][1] - mr0);
            float p02 = __expf(sa[2*j][2] - mr1),   p03 = __expf(sa[2*j][3] - mr1);
            float p10 = __expf(sa[2*j+1][0] - mr0), p11 = __expf(sa[2*j+1][1] - mr0);
            float p12 = __expf(sa[2*j+1][2] - mr1), p13 = __expf(sa[2*j+1][3] - mr1);
            rs0 += p00 + p01 + p10 + p11;
            rs1 += p02 + p03 + p12 + p13;
            pf[j][0] = packh2(p00, p01);
            pf[j][1] = packh2(p02, p03);
            pf[j][2] = packh2(p10, p11);
            pf[j][3] = packh2(p12, p13);
        }
        rs0 += __shfl_xor_sync(~0u, rs0, 1); rs0 += __shfl_xor_sync(~0u, rs0, 2);
        rs1 += __shfl_xor_sync(~0u, rs1, 1); rs1 += __shfl_xor_sync(~0u, rs1, 2);
        l0 += rs0; l1 += rs1;

        // Y += P @ V   (V tile is [tok][d] -> trans ldmatrix gives B[n=d][k=tok])
#pragma unroll
        for (int kf = 0; kf < 4; kf++){
            uint32_t vf[8][2];
#pragma unroll
            for (int p = 0; p < 4; p++){
                uint32_t a = sv + ((kf*16 + (lane & 7) + ((lane >> 3) & 1)*8)*QS
                                   + p*16 + (lane >> 4)*8)*2;
                ldm4t(vf[2*p][0], vf[2*p][1], vf[2*p+1][0], vf[2*p+1][1], a);
            }
#pragma unroll
            for (int nf = 0; nf < 8; nf++) mma16(ya[nf], pf[kf], vf[nf]);
        }
        __syncthreads();
    }

    // normalize and stage to smem fp32 [128][68] (overlaps tiles; safe post-barrier)
    float inv0 = 1.f / l0, inv1 = 1.f / l1;
    float* st = (float*)smh;
#pragma unroll
    for (int nf = 0; nf < 8; nf++){
        int d = nf*8 + t*2;
        st[(wr + g)*68 + d]       = ya[nf][0]*inv0;
        st[(wr + g)*68 + d + 1]   = ya[nf][1]*inv0;
        st[(wr + g + 8)*68 + d]     = ya[nf][2]*inv1;
        st[(wr + g + 8)*68 + d + 1] = ya[nf][3]*inv1;
    }
    __syncthreads();
}

// K2: Y = softmax(qk) @ v  -> g_Yh (fp16) + g_Yf (fp32). grid (5, 192)
__global__ void __launch_bounds__(256) k_av_f(){
    __shared__ __align__(16) __half smh[FL_SMEM];
    int tid = threadIdx.x;
    int m0 = blockIdx.x*128, bh = blockIdx.y;
    size_t ob = (size_t)bh*NP*HD;
    flash_core(smh, g_q + ob, g_k + ob, g_v + ob, m0, tid);

    const float* st = (const float*)smh;
    int r = tid >> 1, hh = tid & 1;
    const float* src = st + r*68 + hh*32;
    size_t o = ob + (size_t)(m0 + r)*HD + hh*32;
#pragma unroll
    for (int i = 0; i < 8; i++)
        ((float4*)(g_Yf + o))[i] = ((const float4*)src)[i];
#pragma unroll
    for (int i = 0; i < 4; i++){
        uint4 u;
        u.x = packh2(src[i*8+0], src[i*8+1]);
        u.y = packh2(src[i*8+2], src[i*8+3]);
        u.z = packh2(src[i*8+4], src[i*8+5]);
        u.w = packh2(src[i*8+6], src[i*8+7]);
        ((uint4*)(g_Yh + o))[i] = u;
    }
}

// K3: Z = softmax(qk) @ Y; hb = (1-2b)Y + 3b*Z -> merged fp16. grid (5, 192)
__global__ void __launch_bounds__(256) k_ay_f(const float* __restrict__ lamb){
    __shared__ __align__(16) __half smh[FL_SMEM];
    int tid = threadIdx.x;
    int m0 = blockIdx.x*128, bh = blockIdx.y;
    int b = bh / HH, h = bh - b*HH;
    size_t ob = (size_t)bh*NP*HD;
    flash_core(smh, g_q + ob, g_k + ob, g_Yh + ob, m0, tid);

    float beta = lamb[h];
    float c0 = 1.f - 2.f*beta, c1 = 3.f*beta;
    const float* st = (const float*)smh;
    int r = tid >> 1, hh = tid & 1;
    int tok = m0 + r;
    if (tok < NN){
        const float* zs = st + r*68 + hh*32;
        const float* yf = g_Yf + ob + (size_t)tok*HD + hh*32;
        __half* dst = g_hb + ((size_t)(b*NN + tok))*CC + h*64 + hh*32;
#pragma unroll
        for (int i = 0; i < 4; i++){
            uint4 u;
            u.x = packh2(c0*yf[i*8+0] + c1*zs[i*8+0], c0*yf[i*8+1] + c1*zs[i*8+1]);
            u.y = packh2(c0*yf[i*8+2] + c1*zs[i*8+2], c0*yf[i*8+3] + c1*zs[i*8+3]);
            u.z = packh2(c0*yf[i*8+4] + c1*zs[i*8+4], c0*yf[i*8+5] + c1*zs[i*8+5]);
            u.w = packh2(c0*yf[i*8+6] + c1*zs[i*8+6], c0*yf[i*8+7] + c1*zs[i*8+7]);
            ((uint4*)dst)[i] = u;
        }
    }
}

// K4: out = hb @ Wp^T + bp (NT, fp32 out). grid (6, 73)
__global__ void __launch_bounds__(256)
k_proj(const float* __restrict__ bp, float* __restrict__ out){
    __shared__ __align__(16) __half sm[4*GBUF];
    int tid = threadIdx.x, lane = tid & 31, wid = tid >> 5;
    int wm = wid >> 1, wn = wid & 1, g = lane >> 2, t = lane & 3;
    int m0 = blockIdx.y*128, n0 = blockIdx.x*128;

    float acc[2][8][4] = {};
    gemm_nt_h(g_hb, CC, m0, MX, g_wp, CC, n0, CC, sm, acc, tid);

#pragma unroll
    for (int mt = 0; mt < 2; mt++)
#pragma unroll
    for (int nf = 0; nf < 8; nf++){
        int col = n0 + wn*64 + nf*8 + t*2;
        float b0 = bp[col], b1 = bp[col + 1];
        int row0 = m0 + wm*32 + mt*16 + g;
#pragma unroll
        for (int rr = 0; rr < 2; rr++){
            int gm = row0 + rr*8;
            if (gm >= MX) continue;
            *(float2*)&out[(size_t)gm*CC + col] =
                make_float2(acc[mt][nf][rr*2] + b0, acc[mt][nf][rr*2+1] + b1);
        }
    }
}

// ======================== host launcher ========================
extern "C" void kernel_launch(void* const* d_in, const int* in_sizes, int n_in,
                              void* d_out, int out_size)
{
    const float* x    = (const float*)d_in[0];
    const float* Wq   = (const float*)d_in[1];
    const float* Wk   = (const float*)d_in[2];
    const float* Wv   = (const float*)d_in[3];
    const float* Wp   = (const float*)d_in[4];
    const float* bp   = (const float*)d_in[5];
    const float* lamb = (const float*)d_in[6];
    float* out = (float*)d_out;

    const int nx8 = MX*CC/8, nw8 = CC*CC/8;
    k_cvt<<<(nx8 + 255)/256, 256>>>(x,  0, nx8);
    k_cvt<<<(nw8 + 255)/256, 256>>>(Wq, 1, nw8);
    k_cvt<<<(nw8 + 255)/256, 256>>>(Wk, 2, nw8);
    k_cvt<<<(nw8 + 255)/256, 256>>>(Wv, 3, nw8);
    k_cvt<<<(nw8 + 255)/256, 256>>>(Wp, 4, nw8);

    k_qkv <<<dim3(CC/128, (MX + 127)/128, 3), 256>>>();
    k_av_f<<<dim3(NP/128, BH), 256>>>();
    k_ay_f<<<dim3(NP/128, BH), 256>>>(lamb);
    k_proj<<<dim3(CC/128, (MX + 127)/128), 256>>>(bp, out);
}

// round 6
// speedup vs baseline: 10.3286x; 1.0807x over previous
#include <cuda_runtime.h>
#include <cuda_fp16.h>
#include <cstdint>

#define Bb 16
#define NN 577
#define NP 640
#define CC 768
#define HH 12
#define HD 64
#define BH (Bb*HH)          // 192
#define MX (Bb*NN)          // 9232
#define SCALE 0.125f

// ---- fp16/fp32 scratch (static device arrays; pads stay zero) ----
static __device__ __half g_xh[(size_t)MX*CC];
static __device__ __half g_wq[(size_t)CC*CC];
static __device__ __half g_wk[(size_t)CC*CC];
static __device__ __half g_wv[(size_t)CC*CC];
static __device__ __half g_wp[(size_t)CC*CC];
static __device__ __half g_q [(size_t)BH*NP*HD];   // [bh][tok][d], q pre-scaled
static __device__ __half g_k [(size_t)BH*NP*HD];
static __device__ __half g_v [(size_t)BH*NP*HD];
static __device__ __half g_Yh[(size_t)BH*NP*HD];   // A@v fp16 [bh][tok][d]
static __device__ float  g_Yf[(size_t)BH*NP*HD];   // A@v fp32 (for epilogue)
static __device__ __half g_hb[(size_t)MX*CC];      // merged-head (b,n,c)

// ======================== low-level helpers (sm_80+ PTX) ========================
__device__ __forceinline__ uint32_t sptr(const void* p){
    return (uint32_t)__cvta_generic_to_shared(p);
}
__device__ __forceinline__ void cpa16(uint32_t dst, const void* src){
    asm volatile("cp.async.cg.shared.global [%0], [%1], 16;\n" :: "r"(dst), "l"(src));
}
#define CP_COMMIT() asm volatile("cp.async.commit_group;\n" ::)
#define CP_WAIT0()  asm volatile("cp.async.wait_group 0;\n" ::)
#define CP_WAIT1()  asm volatile("cp.async.wait_group 1;\n" ::)

__device__ __forceinline__ void ldm4(uint32_t& r0, uint32_t& r1, uint32_t& r2, uint32_t& r3, uint32_t a){
    asm volatile("ldmatrix.sync.aligned.m8n8.x4.shared.b16 {%0,%1,%2,%3}, [%4];"
        : "=r"(r0), "=r"(r1), "=r"(r2), "=r"(r3) : "r"(a));
}
__device__ __forceinline__ void ldm4t(uint32_t& r0, uint32_t& r1, uint32_t& r2, uint32_t& r3, uint32_t a){
    asm volatile("ldmatrix.sync.aligned.m8n8.x4.trans.shared.b16 {%0,%1,%2,%3}, [%4];"
        : "=r"(r0), "=r"(r1), "=r"(r2), "=r"(r3) : "r"(a));
}
__device__ __forceinline__ void mma16(float* c, const uint32_t* a, const uint32_t* b){
    asm volatile("mma.sync.aligned.m16n8k16.row.col.f32.f16.f16.f32 "
        "{%0,%1,%2,%3}, {%4,%5,%6,%7}, {%8,%9}, {%0,%1,%2,%3};"
        : "+f"(c[0]), "+f"(c[1]), "+f"(c[2]), "+f"(c[3])
        : "r"(a[0]), "r"(a[1]), "r"(a[2]), "r"(a[3]), "r"(b[0]), "r"(b[1]));
}
__device__ __forceinline__ uint32_t packh2(float lo, float hi){
    __half2 h = __floats2half2_rn(lo, hi);
    return *reinterpret_cast<uint32_t*>(&h);
}

// ======================== fp16 NT GEMM, 3-stage pipeline ======================
// D[128 x 128] = A[128 x K] * B[128 x K]^T. 256 threads, 8 warps (4m x 2n).
// Per-stage: A tile 128x(32+8pad) halves (10240 B) + B tile same -> 20480 B.
// 3 stages = 61440 B dynamic smem. One __syncthreads per K-iteration.
#define GST 20480           // stage stride (bytes)
#define GEMM_SMEM (3*GST)   // 61440

__device__ __forceinline__ void gemm_nt_h(
    const __half* __restrict__ A, int ldA, int a_r0, int a_clamp,
    const __half* __restrict__ B, int ldB, int b_r0,
    int Ktot, __half* sm, float (&acc)[2][8][4], int tid)
{
    const int lane = tid & 31, wid = tid >> 5;
    const int wm = wid >> 1, wn = wid & 1;
    const uint32_t s0 = sptr(sm);
    const int T = Ktot / 32;

    auto load = [&](int kt){
        uint32_t base = s0 + (kt % 3) * GST;
        int k0 = kt * 32;
#pragma unroll
        for (int i = 0; i < 2; i++){
            int e = tid + i*256;
            int r = e >> 2, c = e & 3;
            int gr = a_r0 + r; if (a_clamp) gr = (gr < a_clamp) ? gr : (a_clamp - 1);
            cpa16(base + r*80 + c*16, A + (size_t)gr*ldA + k0 + c*8);
        }
#pragma unroll
        for (int i = 0; i < 2; i++){
            int e = tid + i*256;
            int r = e >> 2, c = e & 3;
            cpa16(base + 10240 + r*80 + c*16, B + (size_t)(b_r0 + r)*ldB + k0 + c*8);
        }
        CP_COMMIT();
    };

    load(0);
    if (T > 1) load(1);
    for (int kt = 0; kt < T; kt++){
        if (kt + 1 < T) CP_WAIT1(); else CP_WAIT0();
        __syncthreads();
        if (kt + 2 < T) load(kt + 2);
        uint32_t aB = s0 + (kt % 3) * GST;
        uint32_t bB = aB + 10240;
#pragma unroll
        for (int kf = 0; kf < 2; kf++){
            uint32_t af[2][4], bf[8][2];
#pragma unroll
            for (int mt = 0; mt < 2; mt++){
                uint32_t a = aB + ((wm*32 + mt*16 + (lane & 15))*40 + kf*16 + (lane >> 4)*8)*2;
                ldm4(af[mt][0], af[mt][1], af[mt][2], af[mt][3], a);
            }
#pragma unroll
            for (int p = 0; p < 4; p++){
                uint32_t a = bB + ((wn*64 + p*16 + (lane & 7) + ((lane >> 4) & 1)*8)*40
                                   + kf*16 + ((lane >> 3) & 1)*8)*2;
                ldm4(bf[2*p][0], bf[2*p][1], bf[2*p+1][0], bf[2*p+1][1], a);
            }
#pragma unroll
            for (int mt = 0; mt < 2; mt++)
#pragma unroll
                for (int nf = 0; nf < 8; nf++)
                    mma16(acc[mt][nf], af[mt], bf[nf]);
        }
    }
    __syncthreads();
}

// ======================== kernels ========================
// K0: fp32 -> fp16 conversion
__global__ void __launch_bounds__(256) k_cvt(const float* __restrict__ s, int sel, int n8){
    int i = blockIdx.x*256 + threadIdx.x;
    if (i >= n8) return;
    __half* d = (sel == 0) ? g_xh : (sel == 1) ? g_wq : (sel == 2) ? g_wk
              : (sel == 3) ? g_wv : g_wp;
    const float4* s4 = (const float4*)s;
    float4 a = s4[2*i], b = s4[2*i+1];
    uint4 o;
    o.x = packh2(a.x, a.y); o.y = packh2(a.z, a.w);
    o.z = packh2(b.x, b.y); o.w = packh2(b.z, b.w);
    ((uint4*)d)[i] = o;
}

// K1: QKV projection (NT), outputs [bh][tok][d] fp16. grid (6, 73, 3)
__global__ void __launch_bounds__(256) k_qkv(){
    extern __shared__ __align__(16) __half dsm[];
    int tid = threadIdx.x, lane = tid & 31, wid = tid >> 5;
    int wm = wid >> 1, wn = wid & 1, g = lane >> 2, t = lane & 3;
    int z = blockIdx.z, m0 = blockIdx.y*128, n0 = blockIdx.x*128;
    const __half* W = (z == 0) ? g_wq : (z == 1) ? g_wk : g_wv;
    __half* dst = (z == 0) ? g_q : (z == 1) ? g_k : g_v;
    float scale = (z == 0) ? SCALE : 1.f;

    float acc[2][8][4] = {};
    gemm_nt_h(g_xh, CC, m0, MX, W, CC, n0, CC, dsm, acc, tid);

#pragma unroll
    for (int mt = 0; mt < 2; mt++)
#pragma unroll
    for (int nf = 0; nf < 8; nf++){
        int col = n0 + wn*64 + nf*8 + t*2;
        int h = col >> 6, d = col & 63;
        int row0 = m0 + wm*32 + mt*16 + g;
#pragma unroll
        for (int rr = 0; rr < 2; rr++){
            int gm = row0 + rr*8;
            if (gm >= MX) continue;
            int b = gm / NN, n = gm - b*NN;
            uint32_t h2 = packh2(acc[mt][nf][rr*2]*scale, acc[mt][nf][rr*2+1]*scale);
            *(uint32_t*)&dst[(((size_t)(b*HH + h))*NP + n)*HD + d] = h2;
        }
    }
}

// ======================== flash attention core (3-stage K/V pipeline) ==========
// Block: 128 q-rows of one (b,h). 8 warps x 16 rows. Key tiles of 64.
// SMEM: q 128x72 halves (18432 B) + 3 stages x (K 64x72 + V 64x72) (18432 B each)
#define QS 72
#define FST 18432
#define FL_SMEM (18432 + 3*FST)   // 73728 B

__device__ __forceinline__ void flash_core(
    __half* smh, const __half* qg, const __half* kg, const __half* vg,
    int m0, int tid)
{
    const int lane = tid & 31, wid = tid >> 5;
    const int g = lane >> 2, t = lane & 3;
    const int wr = wid*16;
    const uint32_t s0 = sptr(smh);
    const uint32_t sq = s0;
    const int T = NP/64;   // 10

    auto loadkv = [&](int kt){
        uint32_t base = s0 + 18432 + (kt % 3) * FST;
        int tok0 = kt * 64;
#pragma unroll
        for (int i = 0; i < 2; i++){
            int e = tid + i*256;
            int r = e >> 3, c = e & 7;
            cpa16(base + r*(QS*2) + c*16,        kg + (size_t)(tok0 + r)*HD + c*8);
            cpa16(base + 9216 + r*(QS*2) + c*16, vg + (size_t)(tok0 + r)*HD + c*8);
        }
        CP_COMMIT();
    };

    // q tile + first two K/V stages
#pragma unroll
    for (int i = 0; i < 4; i++){
        int e = tid + i*256;
        int r = e >> 3, c = e & 7;
        cpa16(sq + r*(QS*2) + c*16, qg + (size_t)(m0 + r)*HD + c*8);
    }
    CP_COMMIT();
    loadkv(0);
    loadkv(1);

    // wait for q (3 groups pending; q is group 0 -> wait <=2 pending)
    asm volatile("cp.async.wait_group 2;\n" ::);
    __syncthreads();

    uint32_t qf[4][4];
#pragma unroll
    for (int kf = 0; kf < 4; kf++){
        uint32_t a = sq + ((wr + (lane & 15))*QS + kf*16 + (lane >> 4)*8)*2;
        ldm4(qf[kf][0], qf[kf][1], qf[kf][2], qf[kf][3], a);
    }

    float mr0 = -1e30f, mr1 = -1e30f, l0 = 0.f, l1 = 0.f;
    float ya[8][4];
#pragma unroll
    for (int nf = 0; nf < 8; nf++){ ya[nf][0]=0; ya[nf][1]=0; ya[nf][2]=0; ya[nf][3]=0; }

    for (int kt = 0; kt < T; kt++){
        int tok0 = kt*64;
        if (kt + 1 < T) CP_WAIT1(); else CP_WAIT0();
        __syncthreads();
        if (kt + 2 < T) loadkv(kt + 2);
        uint32_t sk = s0 + 18432 + (kt % 3) * FST;
        uint32_t sv = sk + 9216;

        // S = q @ k^T (K=64)
        float sa[8][4];
#pragma unroll
        for (int nf = 0; nf < 8; nf++){ sa[nf][0]=0; sa[nf][1]=0; sa[nf][2]=0; sa[nf][3]=0; }
#pragma unroll
        for (int kf = 0; kf < 4; kf++){
            uint32_t bf[8][2];
#pragma unroll
            for (int p = 0; p < 4; p++){
                uint32_t a = sk + ((p*16 + (lane & 7) + ((lane >> 4) & 1)*8)*QS
                                   + kf*16 + ((lane >> 3) & 1)*8)*2;
                ldm4(bf[2*p][0], bf[2*p][1], bf[2*p+1][0], bf[2*p+1][1], a);
            }
#pragma unroll
            for (int nf = 0; nf < 8; nf++) mma16(sa[nf], qf[kf], bf[nf]);
        }

        // mask invalid keys (only last tile crosses NN)
        if (tok0 + 64 > NN){
#pragma unroll
            for (int nf = 0; nf < 8; nf++){
                int kb = tok0 + nf*8 + t*2;
                if (kb >= NN)     { sa[nf][0] = -1e30f; sa[nf][2] = -1e30f; }
                if (kb + 1 >= NN) { sa[nf][1] = -1e30f; sa[nf][3] = -1e30f; }
            }
        }
        // online softmax (row quad-reduce)
        float tm0 = -1e30f, tm1 = -1e30f;
#pragma unroll
        for (int nf = 0; nf < 8; nf++){
            tm0 = fmaxf(tm0, fmaxf(sa[nf][0], sa[nf][1]));
            tm1 = fmaxf(tm1, fmaxf(sa[nf][2], sa[nf][3]));
        }
        tm0 = fmaxf(tm0, __shfl_xor_sync(~0u, tm0, 1));
        tm0 = fmaxf(tm0, __shfl_xor_sync(~0u, tm0, 2));
        tm1 = fmaxf(tm1, __shfl_xor_sync(~0u, tm1, 1));
        tm1 = fmaxf(tm1, __shfl_xor_sync(~0u, tm1, 2));
        float mn0 = fmaxf(mr0, tm0), mn1 = fmaxf(mr1, tm1);
        float sc0 = __expf(mr0 - mn0), sc1 = __expf(mr1 - mn1);
        mr0 = mn0; mr1 = mn1;
        l0 *= sc0; l1 *= sc1;
#pragma unroll
        for (int nf = 0; nf < 8; nf++){
            ya[nf][0] *= sc0; ya[nf][1] *= sc0; ya[nf][2] *= sc1; ya[nf][3] *= sc1;
        }
        float rs0 = 0.f, rs1 = 0.f;
        uint32_t pf[4][4];
#pragma unroll
        for (int j = 0; j < 4; j++){
            float p00 = __expf(sa[2*j][0] - mr0),   p01 = __expf(sa[2*j][1] - mr0);
            float p02 = __expf(sa[2*j][2] - mr1),   p03 = __expf(sa[2*j][3] - mr1);
            float p10 = __expf(sa[2*j+1][0] - mr0), p11 = __expf(sa[2*j+1][1] - mr0);
            float p12 = __expf(sa[2*j+1][2] - mr1), p13 = __expf(sa[2*j+1][3] - mr1);
            rs0 += p00 + p01 + p10 + p11;
            rs1 += p02 + p03 + p12 + p13;
            pf[j][0] = packh2(p00, p01);
            pf[j][1] = packh2(p02, p03);
            pf[j][2] = packh2(p10, p11);
            pf[j][3] = packh2(p12, p13);
        }
        rs0 += __shfl_xor_sync(~0u, rs0, 1); rs0 += __shfl_xor_sync(~0u, rs0, 2);
        rs1 += __shfl_xor_sync(~0u, rs1, 1); rs1 += __shfl_xor_sync(~0u, rs1, 2);
        l0 += rs0; l1 += rs1;

        // Y += P @ V   (V tile [tok][d]; trans ldmatrix -> B[n=d][k=tok])
#pragma unroll
        for (int kf = 0; kf < 4; kf++){
            uint32_t vf[8][2];
#pragma unroll
            for (int p = 0; p < 4; p++){
                uint32_t a = sv + ((kf*16 + (lane & 7) + ((lane >> 3) & 1)*8)*QS
                                   + p*16 + (lane >> 4)*8)*2;
                ldm4t(vf[2*p][0], vf[2*p][1], vf[2*p+1][0], vf[2*p+1][1], a);
            }
#pragma unroll
            for (int nf = 0; nf < 8; nf++) mma16(ya[nf], pf[kf], vf[nf]);
        }
    }
    __syncthreads();

    // normalize and stage to smem fp32 [128][68]
    float inv0 = 1.f / l0, inv1 = 1.f / l1;
    float* st = (float*)smh;
#pragma unroll
    for (int nf = 0; nf < 8; nf++){
        int d = nf*8 + t*2;
        st[(wr + g)*68 + d]       = ya[nf][0]*inv0;
        st[(wr + g)*68 + d + 1]   = ya[nf][1]*inv0;
        st[(wr + g + 8)*68 + d]     = ya[nf][2]*inv1;
        st[(wr + g + 8)*68 + d + 1] = ya[nf][3]*inv1;
    }
    __syncthreads();
}

// K2: Y = softmax(qk) @ v  -> g_Yh (fp16) + g_Yf (fp32). grid (5, 192)
__global__ void __launch_bounds__(256) k_av_f(){
    extern __shared__ __align__(16) __half dsm[];
    int tid = threadIdx.x;
    int m0 = blockIdx.x*128, bh = blockIdx.y;
    size_t ob = (size_t)bh*NP*HD;
    flash_core(dsm, g_q + ob, g_k + ob, g_v + ob, m0, tid);

    const float* st = (const float*)dsm;
    int r = tid >> 1, hh = tid & 1;
    const float* src = st + r*68 + hh*32;
    size_t o = ob + (size_t)(m0 + r)*HD + hh*32;
#pragma unroll
    for (int i = 0; i < 8; i++)
        ((float4*)(g_Yf + o))[i] = ((const float4*)src)[i];
#pragma unroll
    for (int i = 0; i < 4; i++){
        uint4 u;
        u.x = packh2(src[i*8+0], src[i*8+1]);
        u.y = packh2(src[i*8+2], src[i*8+3]);
        u.z = packh2(src[i*8+4], src[i*8+5]);
        u.w = packh2(src[i*8+6], src[i*8+7]);
        ((uint4*)(g_Yh + o))[i] = u;
    }
}

// K3: Z = softmax(qk) @ Y; hb = (1-2b)Y + 3b*Z -> merged fp16. grid (5, 192)
__global__ void __launch_bounds__(256) k_ay_f(const float* __restrict__ lamb){
    extern __shared__ __align__(16) __half dsm[];
    int tid = threadIdx.x;
    int m0 = blockIdx.x*128, bh = blockIdx.y;
    int b = bh / HH, h = bh - b*HH;
    size_t ob = (size_t)bh*NP*HD;
    flash_core(dsm, g_q + ob, g_k + ob, g_Yh + ob, m0, tid);

    float beta = lamb[h];
    float c0 = 1.f - 2.f*beta, c1 = 3.f*beta;
    const float* st = (const float*)dsm;
    int r = tid >> 1, hh = tid & 1;
    int tok = m0 + r;
    if (tok < NN){
        const float* zs = st + r*68 + hh*32;
        const float* yf = g_Yf + ob + (size_t)tok*HD + hh*32;
        __half* dst = g_hb + ((size_t)(b*NN + tok))*CC + h*64 + hh*32;
#pragma unroll
        for (int i = 0; i < 4; i++){
            uint4 u;
            u.x = packh2(c0*yf[i*8+0] + c1*zs[i*8+0], c0*yf[i*8+1] + c1*zs[i*8+1]);
            u.y = packh2(c0*yf[i*8+2] + c1*zs[i*8+2], c0*yf[i*8+3] + c1*zs[i*8+3]);
            u.z = packh2(c0*yf[i*8+4] + c1*zs[i*8+4], c0*yf[i*8+5] + c1*zs[i*8+5]);
            u.w = packh2(c0*yf[i*8+6] + c1*zs[i*8+6], c0*yf[i*8+7] + c1*zs[i*8+7]);
            ((uint4*)dst)[i] = u;
        }
    }
}

// K4: out = hb @ Wp^T + bp (NT, fp32 out). grid (6, 73)
__global__ void __launch_bounds__(256)
k_proj(const float* __restrict__ bp, float* __restrict__ out){
    extern __shared__ __align__(16) __half dsm[];
    int tid = threadIdx.x, lane = tid & 31, wid = tid >> 5;
    int wm = wid >> 1, wn = wid & 1, g = lane >> 2, t = lane & 3;
    int m0 = blockIdx.y*128, n0 = blockIdx.x*128;

    float acc[2][8][4] = {};
    gemm_nt_h(g_hb, CC, m0, MX, g_wp, CC, n0, CC, dsm, acc, tid);

#pragma unroll
    for (int mt = 0; mt < 2; mt++)
#pragma unroll
    for (int nf = 0; nf < 8; nf++){
        int col = n0 + wn*64 + nf*8 + t*2;
        float b0 = bp[col], b1 = bp[col + 1];
        int row0 = m0 + wm*32 + mt*16 + g;
#pragma unroll
        for (int rr = 0; rr < 2; rr++){
            int gm = row0 + rr*8;
            if (gm >= MX) continue;
            *(float2*)&out[(size_t)gm*CC + col] =
                make_float2(acc[mt][nf][rr*2] + b0, acc[mt][nf][rr*2+1] + b1);
        }
    }
}

// ======================== host launcher ========================
extern "C" void kernel_launch(void* const* d_in, const int* in_sizes, int n_in,
                              void* d_out, int out_size)
{
    const float* x    = (const float*)d_in[0];
    const float* Wq   = (const float*)d_in[1];
    const float* Wk   = (const float*)d_in[2];
    const float* Wv   = (const float*)d_in[3];
    const float* Wp   = (const float*)d_in[4];
    const float* bp   = (const float*)d_in[5];
    const float* lamb = (const float*)d_in[6];
    float* out = (float*)d_out;

    static bool attr_done = false;
    if (!attr_done){
        cudaFuncSetAttribute(k_qkv,  cudaFuncAttributeMaxDynamicSharedMemorySize, GEMM_SMEM);
        cudaFuncSetAttribute(k_proj, cudaFuncAttributeMaxDynamicSharedMemorySize, GEMM_SMEM);
        cudaFuncSetAttribute(k_av_f, cudaFuncAttributeMaxDynamicSharedMemorySize, FL_SMEM);
        cudaFuncSetAttribute(k_ay_f, cudaFuncAttributeMaxDynamicSharedMemorySize, FL_SMEM);
        attr_done = true;
    }

    const int nx8 = MX*CC/8, nw8 = CC*CC/8;
    k_cvt<<<(nx8 + 255)/256, 256>>>(x,  0, nx8);
    k_cvt<<<(nw8 + 255)/256, 256>>>(Wq, 1, nw8);
    k_cvt<<<(nw8 + 255)/256, 256>>>(Wk, 2, nw8);
    k_cvt<<<(nw8 + 255)/256, 256>>>(Wv, 3, nw8);
    k_cvt<<<(nw8 + 255)/256, 256>>>(Wp, 4, nw8);

    k_qkv <<<dim3(CC/128, (MX + 127)/128, 3), 256, GEMM_SMEM>>>();
    k_av_f<<<dim3(NP/128, BH), 256, FL_SMEM>>>();
    k_ay_f<<<dim3(NP/128, BH), 256, FL_SMEM>>>(lamb);
    k_proj<<<dim3(CC/128, (MX + 127)/128), 256, GEMM_SMEM>>>(bp, out);
}

// round 7
// speedup vs baseline: 11.1193x; 1.0766x over previous
#include <cuda_runtime.h>
#include <cuda_fp16.h>
#include <cstdint>

#define Bb 16
#define NN 577
#define NP 640
#define CC 768
#define HH 12
#define HD 64
#define BH (Bb*HH)          // 192
#define MX (Bb*NN)          // 9232
#define SCALE 0.125f

// ---- fp16/fp32 scratch (static device arrays; pads stay zero) ----
static __device__ __half g_xh[(size_t)MX*CC];
static __device__ __half g_wq[(size_t)CC*CC];
static __device__ __half g_wk[(size_t)CC*CC];
static __device__ __half g_wv[(size_t)CC*CC];
static __device__ __half g_wp[(size_t)CC*CC];
static __device__ __half g_q [(size_t)BH*NP*HD];   // [bh][tok][d], q pre-scaled
static __device__ __half g_k [(size_t)BH*NP*HD];
static __device__ __half g_v [(size_t)BH*NP*HD];
static __device__ __half g_Yh[(size_t)BH*NP*HD];   // A@v fp16 [bh][tok][d]
static __device__ float  g_Yf[(size_t)BH*NP*HD];   // A@v fp32 (for epilogue)
static __device__ float  g_mpl[(size_t)BH*NP];     // rowwise m + ln(l)
static __device__ __half g_hb[(size_t)MX*CC];      // merged-head (b,n,c)

// ======================== low-level helpers (sm_80+ PTX) ========================
__device__ __forceinline__ uint32_t sptr(const void* p){
    return (uint32_t)__cvta_generic_to_shared(p);
}
__device__ __forceinline__ void cpa16(uint32_t dst, const void* src){
    asm volatile("cp.async.cg.shared.global [%0], [%1], 16;\n" :: "r"(dst), "l"(src));
}
#define CP_COMMIT() asm volatile("cp.async.commit_group;\n" ::)
#define CP_WAIT0()  asm volatile("cp.async.wait_group 0;\n" ::)
#define CP_WAIT1()  asm volatile("cp.async.wait_group 1;\n" ::)

__device__ __forceinline__ void ldm4(uint32_t& r0, uint32_t& r1, uint32_t& r2, uint32_t& r3, uint32_t a){
    asm volatile("ldmatrix.sync.aligned.m8n8.x4.shared.b16 {%0,%1,%2,%3}, [%4];"
        : "=r"(r0), "=r"(r1), "=r"(r2), "=r"(r3) : "r"(a));
}
__device__ __forceinline__ void ldm4t(uint32_t& r0, uint32_t& r1, uint32_t& r2, uint32_t& r3, uint32_t a){
    asm volatile("ldmatrix.sync.aligned.m8n8.x4.trans.shared.b16 {%0,%1,%2,%3}, [%4];"
        : "=r"(r0), "=r"(r1), "=r"(r2), "=r"(r3) : "r"(a));
}
__device__ __forceinline__ void mma16(float* c, const uint32_t* a, const uint32_t* b){
    asm volatile("mma.sync.aligned.m16n8k16.row.col.f32.f16.f16.f32 "
        "{%0,%1,%2,%3}, {%4,%5,%6,%7}, {%8,%9}, {%0,%1,%2,%3};"
        : "+f"(c[0]), "+f"(c[1]), "+f"(c[2]), "+f"(c[3])
        : "r"(a[0]), "r"(a[1]), "r"(a[2]), "r"(a[3]), "r"(b[0]), "r"(b[1]));
}
__device__ __forceinline__ uint32_t packh2(float lo, float hi){
    __half2 h = __floats2half2_rn(lo, hi);
    return *reinterpret_cast<uint32_t*>(&h);
}
__device__ __forceinline__ float2 h2f(uint32_t u){
    return __half22float2(*reinterpret_cast<__half2*>(&u));
}

// ======================== fp16 NT GEMM, 3-stage pipeline ======================
#define GST 20480           // stage stride (bytes)
#define GEMM_SMEM (3*GST)   // 61440

__device__ __forceinline__ void gemm_nt_h(
    const __half* __restrict__ A, int ldA, int a_r0, int a_clamp,
    const __half* __restrict__ B, int ldB, int b_r0,
    int Ktot, __half* sm, float (&acc)[2][8][4], int tid)
{
    const int lane = tid & 31, wid = tid >> 5;
    const int wm = wid >> 1, wn = wid & 1;
    const uint32_t s0 = sptr(sm);
    const int T = Ktot / 32;

    auto load = [&](int kt){
        uint32_t base = s0 + (kt % 3) * GST;
        int k0 = kt * 32;
#pragma unroll
        for (int i = 0; i < 2; i++){
            int e = tid + i*256;
            int r = e >> 2, c = e & 3;
            int gr = a_r0 + r; if (a_clamp) gr = (gr < a_clamp) ? gr : (a_clamp - 1);
            cpa16(base + r*80 + c*16, A + (size_t)gr*ldA + k0 + c*8);
        }
#pragma unroll
        for (int i = 0; i < 2; i++){
            int e = tid + i*256;
            int r = e >> 2, c = e & 3;
            cpa16(base + 10240 + r*80 + c*16, B + (size_t)(b_r0 + r)*ldB + k0 + c*8);
        }
        CP_COMMIT();
    };

    load(0);
    if (T > 1) load(1);
    for (int kt = 0; kt < T; kt++){
        if (kt + 1 < T) CP_WAIT1(); else CP_WAIT0();
        __syncthreads();
        if (kt + 2 < T) load(kt + 2);
        uint32_t aB = s0 + (kt % 3) * GST;
        uint32_t bB = aB + 10240;
#pragma unroll
        for (int kf = 0; kf < 2; kf++){
            uint32_t af[2][4], bf[8][2];
#pragma unroll
            for (int mt = 0; mt < 2; mt++){
                uint32_t a = aB + ((wm*32 + mt*16 + (lane & 15))*40 + kf*16 + (lane >> 4)*8)*2;
                ldm4(af[mt][0], af[mt][1], af[mt][2], af[mt][3], a);
            }
#pragma unroll
            for (int p = 0; p < 4; p++){
                uint32_t a = bB + ((wn*64 + p*16 + (lane & 7) + ((lane >> 4) & 1)*8)*40
                                   + kf*16 + ((lane >> 3) & 1)*8)*2;
                ldm4(bf[2*p][0], bf[2*p][1], bf[2*p+1][0], bf[2*p+1][1], a);
            }
#pragma unroll
            for (int mt = 0; mt < 2; mt++)
#pragma unroll
                for (int nf = 0; nf < 8; nf++)
                    mma16(acc[mt][nf], af[mt], bf[nf]);
        }
    }
    __syncthreads();
}

// ======================== kernels ========================
#define NX8 (MX*CC/8)
#define NW8 (CC*CC/8)
#define NCVT (NX8 + 4*NW8)

// K0: merged fp32 -> fp16 conversion (x + 4 weights in one launch)
__global__ void __launch_bounds__(256) k_cvt_all(
    const float* __restrict__ x,  const float* __restrict__ wq,
    const float* __restrict__ wk, const float* __restrict__ wv,
    const float* __restrict__ wp)
{
    int i = blockIdx.x*256 + threadIdx.x;
    if (i >= NCVT) return;
    const float* s; __half* d; int off;
    if (i < NX8){ s = x; d = g_xh; off = i; }
    else {
        int j = i - NX8, w = j / NW8; off = j - w*NW8;
        s = (w == 0) ? wq : (w == 1) ? wk : (w == 2) ? wv : wp;
        d = (w == 0) ? g_wq : (w == 1) ? g_wk : (w == 2) ? g_wv : g_wp;
    }
    const float4* s4 = (const float4*)s;
    float4 a = s4[2*off], b = s4[2*off+1];
    uint4 o;
    o.x = packh2(a.x, a.y); o.y = packh2(a.z, a.w);
    o.z = packh2(b.x, b.y); o.w = packh2(b.z, b.w);
    ((uint4*)d)[off] = o;
}

// K1: QKV projection (NT), outputs [bh][tok][d] fp16. grid (6, 73, 3)
__global__ void __launch_bounds__(256) k_qkv(){
    extern __shared__ __align__(16) __half dsm[];
    int tid = threadIdx.x, lane = tid & 31, wid = tid >> 5;
    int wm = wid >> 1, wn = wid & 1, g = lane >> 2, t = lane & 3;
    int z = blockIdx.z, m0 = blockIdx.y*128, n0 = blockIdx.x*128;
    const __half* W = (z == 0) ? g_wq : (z == 1) ? g_wk : g_wv;
    __half* dst = (z == 0) ? g_q : (z == 1) ? g_k : g_v;
    float scale = (z == 0) ? SCALE : 1.f;

    float acc[2][8][4] = {};
    gemm_nt_h(g_xh, CC, m0, MX, W, CC, n0, CC, dsm, acc, tid);

#pragma unroll
    for (int mt = 0; mt < 2; mt++)
#pragma unroll
    for (int nf = 0; nf < 8; nf++){
        int col = n0 + wn*64 + nf*8 + t*2;
        int h = col >> 6, d = col & 63;
        int row0 = m0 + wm*32 + mt*16 + g;
#pragma unroll
        for (int rr = 0; rr < 2; rr++){
            int gm = row0 + rr*8;
            if (gm >= MX) continue;
            int b = gm / NN, n = gm - b*NN;
            uint32_t h2 = packh2(acc[mt][nf][rr*2]*scale, acc[mt][nf][rr*2+1]*scale);
            *(uint32_t*)&dst[(((size_t)(b*HH + h))*NP + n)*HD + d] = h2;
        }
    }
}

// ======================== flash attention core ========================
// Keys 0..575 = 9 full 64-tiles (NO masking); key 576 = scalar rank-1 tail.
// FIRST=true : online softmax, writes mpl = m + ln(l), outputs normalized Y.
// FIRST=false: uses precomputed mpl, P = exp(s - mpl), no rescale/normalize.
#define QS 72
#define FST 18432
#define TAILB 73728                    // byte offset of 256B tail region (k576|v576)
#define FL_SMEM (18432 + 3*FST + 256)  // 73984 B
#define TKV 9

template<bool FIRST>
__device__ __forceinline__ void flash_core(
    __half* smh, const __half* qg, const __half* kg, const __half* vg,
    float* __restrict__ mpl, int m0, int tid)
{
    const int lane = tid & 31, wid = tid >> 5;
    const int g = lane >> 2, t = lane & 3;
    const int wr = wid*16;
    const uint32_t s0 = sptr(smh);
    const uint32_t sq = s0;

    auto loadkv = [&](int kt){
        uint32_t base = s0 + 18432 + (kt % 3) * FST;
        int tok0 = kt * 64;
#pragma unroll
        for (int i = 0; i < 2; i++){
            int e = tid + i*256;
            int r = e >> 3, c = e & 7;
            cpa16(base + r*(QS*2) + c*16,        kg + (size_t)(tok0 + r)*HD + c*8);
            cpa16(base + 9216 + r*(QS*2) + c*16, vg + (size_t)(tok0 + r)*HD + c*8);
        }
        CP_COMMIT();
    };

    // q tile + tail rows (k576, v576) in group 0; first two K/V stages after
#pragma unroll
    for (int i = 0; i < 4; i++){
        int e = tid + i*256;
        int r = e >> 3, c = e & 7;
        cpa16(sq + r*(QS*2) + c*16, qg + (size_t)(m0 + r)*HD + c*8);
    }
    if (tid < 8)       cpa16(s0 + TAILB + tid*16,        kg + (size_t)(NN-1)*HD + tid*8);
    else if (tid < 16) cpa16(s0 + TAILB + 128 + (tid-8)*16, vg + (size_t)(NN-1)*HD + (tid-8)*8);
    CP_COMMIT();
    loadkv(0);
    loadkv(1);

    float mpl0, mpl1;
    if (!FIRST){
        mpl0 = mpl[m0 + wr + g];
        mpl1 = mpl[m0 + wr + g + 8];
    }

    asm volatile("cp.async.wait_group 2;\n" ::);   // q + tail ready
    __syncthreads();

    uint32_t qf[4][4];
#pragma unroll
    for (int kf = 0; kf < 4; kf++){
        uint32_t a = sq + ((wr + (lane & 15))*QS + kf*16 + (lane >> 4)*8)*2;
        ldm4(qf[kf][0], qf[kf][1], qf[kf][2], qf[kf][3], a);
    }

    float mr0 = -1e30f, mr1 = -1e30f, l0 = 0.f, l1 = 0.f;
    float ya[8][4];
#pragma unroll
    for (int nf = 0; nf < 8; nf++){ ya[nf][0]=0; ya[nf][1]=0; ya[nf][2]=0; ya[nf][3]=0; }

    for (int kt = 0; kt < TKV; kt++){
        if (kt + 1 < TKV) CP_WAIT1(); else CP_WAIT0();
        __syncthreads();
        if (kt + 2 < TKV) loadkv(kt + 2);
        uint32_t sk = s0 + 18432 + (kt % 3) * FST;
        uint32_t sv = sk + 9216;

        // S = q @ k^T (K=64)
        float sa[8][4];
#pragma unroll
        for (int nf = 0; nf < 8; nf++){ sa[nf][0]=0; sa[nf][1]=0; sa[nf][2]=0; sa[nf][3]=0; }
#pragma unroll
        for (int kf = 0; kf < 4; kf++){
            uint32_t bf[8][2];
#pragma unroll
            for (int p = 0; p < 4; p++){
                uint32_t a = sk + ((p*16 + (lane & 7) + ((lane >> 4) & 1)*8)*QS
                                   + kf*16 + ((lane >> 3) & 1)*8)*2;
                ldm4(bf[2*p][0], bf[2*p][1], bf[2*p+1][0], bf[2*p+1][1], a);
            }
#pragma unroll
            for (int nf = 0; nf < 8; nf++) mma16(sa[nf], qf[kf], bf[nf]);
        }

        uint32_t pf[4][4];
        if (FIRST){
            // online softmax (row quad-reduce)
            float tm0 = -1e30f, tm1 = -1e30f;
#pragma unroll
            for (int nf = 0; nf < 8; nf++){
                tm0 = fmaxf(tm0, fmaxf(sa[nf][0], sa[nf][1]));
                tm1 = fmaxf(tm1, fmaxf(sa[nf][2], sa[nf][3]));
            }
            tm0 = fmaxf(tm0, __shfl_xor_sync(~0u, tm0, 1));
            tm0 = fmaxf(tm0, __shfl_xor_sync(~0u, tm0, 2));
            tm1 = fmaxf(tm1, __shfl_xor_sync(~0u, tm1, 1));
            tm1 = fmaxf(tm1, __shfl_xor_sync(~0u, tm1, 2));
            float mn0 = fmaxf(mr0, tm0), mn1 = fmaxf(mr1, tm1);
            float sc0 = __expf(mr0 - mn0), sc1 = __expf(mr1 - mn1);
            mr0 = mn0; mr1 = mn1;
            l0 *= sc0; l1 *= sc1;
#pragma unroll
            for (int nf = 0; nf < 8; nf++){
                ya[nf][0] *= sc0; ya[nf][1] *= sc0; ya[nf][2] *= sc1; ya[nf][3] *= sc1;
            }
            float rs0 = 0.f, rs1 = 0.f;
#pragma unroll
            for (int j = 0; j < 4; j++){
                float p00 = __expf(sa[2*j][0] - mr0),   p01 = __expf(sa[2*j][1] - mr0);
                float p02 = __expf(sa[2*j][2] - mr1),   p03 = __expf(sa[2*j][3] - mr1);
                float p10 = __expf(sa[2*j+1][0] - mr0), p11 = __expf(sa[2*j+1][1] - mr0);
                float p12 = __expf(sa[2*j+1][2] - mr1), p13 = __expf(sa[2*j+1][3] - mr1);
                rs0 += p00 + p01 + p10 + p11;
                rs1 += p02 + p03 + p12 + p13;
                pf[j][0] = packh2(p00, p01);
                pf[j][1] = packh2(p02, p03);
                pf[j][2] = packh2(p10, p11);
                pf[j][3] = packh2(p12, p13);
            }
            rs0 += __shfl_xor_sync(~0u, rs0, 1); rs0 += __shfl_xor_sync(~0u, rs0, 2);
            rs1 += __shfl_xor_sync(~0u, rs1, 1); rs1 += __shfl_xor_sync(~0u, rs1, 2);
            l0 += rs0; l1 += rs1;
        } else {
            // P = exp(s - mpl): no max tracking, no rescale, no row sums
#pragma unroll
            for (int j = 0; j < 4; j++){
                pf[j][0] = packh2(__expf(sa[2*j][0] - mpl0),   __expf(sa[2*j][1] - mpl0));
                pf[j][1] = packh2(__expf(sa[2*j][2] - mpl1),   __expf(sa[2*j][3] - mpl1));
                pf[j][2] = packh2(__expf(sa[2*j+1][0] - mpl0), __expf(sa[2*j+1][1] - mpl0));
                pf[j][3] = packh2(__expf(sa[2*j+1][2] - mpl1), __expf(sa[2*j+1][3] - mpl1));
            }
        }

        // Y += P @ V   (V tile [tok][d]; trans ldmatrix -> B[n=d][k=tok])
#pragma unroll
        for (int kf = 0; kf < 4; kf++){
            uint32_t vf[8][2];
#pragma unroll
            for (int p = 0; p < 4; p++){
                uint32_t a = sv + ((kf*16 + (lane & 7) + ((lane >> 3) & 1)*8)*QS
                                   + p*16 + (lane >> 4)*8)*2;
                ldm4t(vf[2*p][0], vf[2*p][1], vf[2*p+1][0], vf[2*p+1][1], a);
            }
#pragma unroll
            for (int nf = 0; nf < 8; nf++) mma16(ya[nf], pf[kf], vf[nf]);
        }
    }

    // ---- tail: key 576 (rank-1) ----
    {
        const __half2* kt2 = (const __half2*)(smh + TAILB/2);       // 32 half2 (k576)
        const __half2* vt2 = kt2 + 32;                              // 32 half2 (v576)
        float s0v = 0.f, s1v = 0.f;
#pragma unroll
        for (int kf = 0; kf < 4; kf++){
            float2 klo = __half22float2(kt2[kf*8 + t]);
            float2 khi = __half22float2(kt2[kf*8 + 4 + t]);
            float2 q0l = h2f(qf[kf][0]), q1l = h2f(qf[kf][1]);
            float2 q0h = h2f(qf[kf][2]), q1h = h2f(qf[kf][3]);
            s0v += q0l.x*klo.x + q0l.y*klo.y + q0h.x*khi.x + q0h.y*khi.y;
            s1v += q1l.x*klo.x + q1l.y*klo.y + q1h.x*khi.x + q1h.y*khi.y;
        }
        s0v += __shfl_xor_sync(~0u, s0v, 1); s0v += __shfl_xor_sync(~0u, s0v, 2);
        s1v += __shfl_xor_sync(~0u, s1v, 1); s1v += __shfl_xor_sync(~0u, s1v, 2);

        if (FIRST){
            float mn0 = fmaxf(mr0, s0v), mn1 = fmaxf(mr1, s1v);
            float sc0 = __expf(mr0 - mn0), sc1 = __expf(mr1 - mn1);
            float p0 = __expf(s0v - mn0), p1 = __expf(s1v - mn1);
            l0 = l0*sc0 + p0; l1 = l1*sc1 + p1;
#pragma unroll
            for (int nf = 0; nf < 8; nf++){
                float2 v2 = __half22float2(vt2[nf*4 + t]);
                ya[nf][0] = ya[nf][0]*sc0 + p0*v2.x;
                ya[nf][1] = ya[nf][1]*sc0 + p0*v2.y;
                ya[nf][2] = ya[nf][2]*sc1 + p1*v2.x;
                ya[nf][3] = ya[nf][3]*sc1 + p1*v2.y;
            }
            if (t == 0){
                mpl[m0 + wr + g]     = mn0 + __logf(l0);
                mpl[m0 + wr + g + 8] = mn1 + __logf(l1);
            }
            mr0 = mn0; mr1 = mn1;
        } else {
            float p0 = __expf(s0v - mpl0), p1 = __expf(s1v - mpl1);
#pragma unroll
            for (int nf = 0; nf < 8; nf++){
                float2 v2 = __half22float2(vt2[nf*4 + t]);
                ya[nf][0] += p0*v2.x; ya[nf][1] += p0*v2.y;
                ya[nf][2] += p1*v2.x; ya[nf][3] += p1*v2.y;
            }
        }
    }
    __syncthreads();

    // normalize (FIRST only) and stage to smem fp32 [128][68]
    float inv0 = FIRST ? (1.f / l0) : 1.f;
    float inv1 = FIRST ? (1.f / l1) : 1.f;
    float* st = (float*)smh;
#pragma unroll
    for (int nf = 0; nf < 8; nf++){
        int d = nf*8 + t*2;
        st[(wr + g)*68 + d]         = ya[nf][0]*inv0;
        st[(wr + g)*68 + d + 1]     = ya[nf][1]*inv0;
        st[(wr + g + 8)*68 + d]     = ya[nf][2]*inv1;
        st[(wr + g + 8)*68 + d + 1] = ya[nf][3]*inv1;
    }
    __syncthreads();
}

// K2: Y = softmax(qk) @ v  -> g_Yh (fp16) + g_Yf (fp32) + g_mpl. grid (5, 192)
__global__ void __launch_bounds__(256) k_av_f(){
    extern __shared__ __align__(16) __half dsm[];
    int tid = threadIdx.x;
    int m0 = blockIdx.x*128, bh = blockIdx.y;
    size_t ob = (size_t)bh*NP*HD;
    flash_core<true>(dsm, g_q + ob, g_k + ob, g_v + ob, g_mpl + (size_t)bh*NP, m0, tid);

    const float* st = (const float*)dsm;
    int r = tid >> 1, hh = tid & 1;
    const float* src = st + r*68 + hh*32;
    size_t o = ob + (size_t)(m0 + r)*HD + hh*32;
#pragma unroll
    for (int i = 0; i < 8; i++)
        ((float4*)(g_Yf + o))[i] = ((const float4*)src)[i];
#pragma unroll
    for (int i = 0; i < 4; i++){
        uint4 u;
        u.x = packh2(src[i*8+0], src[i*8+1]);
        u.y = packh2(src[i*8+2], src[i*8+3]);
        u.z = packh2(src[i*8+4], src[i*8+5]);
        u.w = packh2(src[i*8+6], src[i*8+7]);
        ((uint4*)(g_Yh + o))[i] = u;
    }
}

// K3: Z = softmax(qk) @ Y; hb = (1-2b)Y + 3b*Z -> merged fp16. grid (5, 192)
__global__ void __launch_bounds__(256) k_ay_f(const float* __restrict__ lamb){
    extern __shared__ __align__(16) __half dsm[];
    int tid = threadIdx.x;
    int m0 = blockIdx.x*128, bh = blockIdx.y;
    int b = bh / HH, h = bh - b*HH;
    size_t ob = (size_t)bh*NP*HD;
    flash_core<false>(dsm, g_q + ob, g_k + ob, g_Yh + ob, g_mpl + (size_t)bh*NP, m0, tid);

    float beta = lamb[h];
    float c0 = 1.f - 2.f*beta, c1 = 3.f*beta;
    const float* st = (const float*)dsm;
    int r = tid >> 1, hh = tid & 1;
    int tok = m0 + r;
    if (tok < NN){
        const float* zs = st + r*68 + hh*32;
        const float* yf = g_Yf + ob + (size_t)tok*HD + hh*32;
        __half* dst = g_hb + ((size_t)(b*NN + tok))*CC + h*64 + hh*32;
#pragma unroll
        for (int i = 0; i < 4; i++){
            uint4 u;
            u.x = packh2(c0*yf[i*8+0] + c1*zs[i*8+0], c0*yf[i*8+1] + c1*zs[i*8+1]);
            u.y = packh2(c0*yf[i*8+2] + c1*zs[i*8+2], c0*yf[i*8+3] + c1*zs[i*8+3]);
            u.z = packh2(c0*yf[i*8+4] + c1*zs[i*8+4], c0*yf[i*8+5] + c1*zs[i*8+5]);
            u.w = packh2(c0*yf[i*8+6] + c1*zs[i*8+6], c0*yf[i*8+7] + c1*zs[i*8+7]);
            ((uint4*)dst)[i] = u;
        }
    }
}

// K4: out = hb @ Wp^T + bp (NT, fp32 out). grid (6, 73)
__global__ void __launch_bounds__(256)
k_proj(const float* __restrict__ bp, float* __restrict__ out){
    extern __shared__ __align__(16) __half dsm[];
    int tid = threadIdx.x, lane = tid & 31, wid = tid >> 5;
    int wm = wid >> 1, wn = wid & 1, g = lane >> 2, t = lane & 3;
    int m0 = blockIdx.y*128, n0 = blockIdx.x*128;

    float acc[2][8][4] = {};
    gemm_nt_h(g_hb, CC, m0, MX, g_wp, CC, n0, CC, dsm, acc, tid);

#pragma unroll
    for (int mt = 0; mt < 2; mt++)
#pragma unroll
    for (int nf = 0; nf < 8; nf++){
        int col = n0 + wn*64 + nf*8 + t*2;
        float b0 = bp[col], b1 = bp[col + 1];
        int row0 = m0 + wm*32 + mt*16 + g;
#pragma unroll
        for (int rr = 0; rr < 2; rr++){
            int gm = row0 + rr*8;
            if (gm >= MX) continue;
            *(float2*)&out[(size_t)gm*CC + col] =
                make_float2(acc[mt][nf][rr*2] + b0, acc[mt][nf][rr*2+1] + b1);
        }
    }
}

// ======================== host launcher ========================
extern "C" void kernel_launch(void* const* d_in, const int* in_sizes, int n_in,
                              void* d_out, int out_size)
{
    const float* x    = (const float*)d_in[0];
    const float* Wq   = (const float*)d_in[1];
    const float* Wk   = (const float*)d_in[2];
    const float* Wv   = (const float*)d_in[3];
    const float* Wp   = (const float*)d_in[4];
    const float* bp   = (const float*)d_in[5];
    const float* lamb = (const float*)d_in[6];
    float* out = (float*)d_out;

    static bool attr_done = false;
    if (!attr_done){
        cudaFuncSetAttribute(k_qkv,  cudaFuncAttributeMaxDynamicSharedMemorySize, GEMM_SMEM);
        cudaFuncSetAttribute(k_proj, cudaFuncAttributeMaxDynamicSharedMemorySize, GEMM_SMEM);
        cudaFuncSetAttribute(k_av_f, cudaFuncAttributeMaxDynamicSharedMemorySize, FL_SMEM);
        cudaFuncSetAttribute(k_ay_f, cudaFuncAttributeMaxDynamicSharedMemorySize, FL_SMEM);
        attr_done = true;
    }

    k_cvt_all<<<(NCVT + 255)/256, 256>>>(x, Wq, Wk, Wv, Wp);
    k_qkv <<<dim3(CC/128, (MX + 127)/128, 3), 256, GEMM_SMEM>>>();
    k_av_f<<<dim3(NP/128, BH), 256, FL_SMEM>>>();
    k_ay_f<<<dim3(NP/128, BH), 256, FL_SMEM>>>(lamb);
    k_proj<<<dim3(CC/128, (MX + 127)/128), 256, GEMM_SMEM>>>(bp, out);
}

// round 8
// speedup vs baseline: 11.4840x; 1.0328x over previous
#include <cuda_runtime.h>
#include <cuda_fp16.h>
#include <cstdint>

#define Bb 16
#define NN 577
#define NP 640
#define CC 768
#define HH 12
#define HD 64
#define BH (Bb*HH)          // 192
#define MX (Bb*NN)          // 9232
#define SCALE 0.125f

// ---- fp16/fp32 scratch (static device arrays; pads stay zero) ----
static __device__ __half g_xh[(size_t)MX*CC];
static __device__ __half g_wq[(size_t)CC*CC];
static __device__ __half g_wk[(size_t)CC*CC];
static __device__ __half g_wv[(size_t)CC*CC];
static __device__ __half g_wp[(size_t)CC*CC];
static __device__ __half g_q [(size_t)BH*NP*HD];   // [bh][tok][d], q pre-scaled
static __device__ __half g_k [(size_t)BH*NP*HD];
static __device__ __half g_v [(size_t)BH*NP*HD];
static __device__ __half g_Yh[(size_t)BH*NP*HD];   // A@v fp16 [bh][tok][d]
static __device__ float  g_Yf[(size_t)BH*NP*HD];   // A@v fp32 (for epilogue)
static __device__ float  g_mpl[(size_t)BH*NP];     // rowwise m + ln(l)
static __device__ __half g_hb[(size_t)MX*CC];      // merged-head (b,n,c)

// ======================== low-level helpers (sm_80+ PTX) ========================
__device__ __forceinline__ uint32_t sptr(const void* p){
    return (uint32_t)__cvta_generic_to_shared(p);
}
__device__ __forceinline__ void cpa16(uint32_t dst, const void* src){
    asm volatile("cp.async.cg.shared.global [%0], [%1], 16;\n" :: "r"(dst), "l"(src));
}
#define CP_COMMIT() asm volatile("cp.async.commit_group;\n" ::)
#define CP_WAIT0()  asm volatile("cp.async.wait_group 0;\n" ::)
#define CP_WAIT1()  asm volatile("cp.async.wait_group 1;\n" ::)

__device__ __forceinline__ void ldm4(uint32_t& r0, uint32_t& r1, uint32_t& r2, uint32_t& r3, uint32_t a){
    asm volatile("ldmatrix.sync.aligned.m8n8.x4.shared.b16 {%0,%1,%2,%3}, [%4];"
        : "=r"(r0), "=r"(r1), "=r"(r2), "=r"(r3) : "r"(a));
}
__device__ __forceinline__ void ldm4t(uint32_t& r0, uint32_t& r1, uint32_t& r2, uint32_t& r3, uint32_t a){
    asm volatile("ldmatrix.sync.aligned.m8n8.x4.trans.shared.b16 {%0,%1,%2,%3}, [%4];"
        : "=r"(r0), "=r"(r1), "=r"(r2), "=r"(r3) : "r"(a));
}
__device__ __forceinline__ void mma16(float* c, const uint32_t* a, const uint32_t* b){
    asm volatile("mma.sync.aligned.m16n8k16.row.col.f32.f16.f16.f32 "
        "{%0,%1,%2,%3}, {%4,%5,%6,%7}, {%8,%9}, {%0,%1,%2,%3};"
        : "+f"(c[0]), "+f"(c[1]), "+f"(c[2]), "+f"(c[3])
        : "r"(a[0]), "r"(a[1]), "r"(a[2]), "r"(a[3]), "r"(b[0]), "r"(b[1]));
}
__device__ __forceinline__ uint32_t packh2(float lo, float hi){
    __half2 h = __floats2half2_rn(lo, hi);
    return *reinterpret_cast<uint32_t*>(&h);
}
__device__ __forceinline__ float2 h2f(uint32_t u){
    return __half22float2(*reinterpret_cast<__half2*>(&u));
}

// ======================== fp16 NT GEMM, 3-stage pipeline (unchanged) ===========
#define GST 20480
#define GEMM_SMEM (3*GST)   // 61440

__device__ __forceinline__ void gemm_nt_h(
    const __half* __restrict__ A, int ldA, int a_r0, int a_clamp,
    const __half* __restrict__ B, int ldB, int b_r0,
    int Ktot, __half* sm, float (&acc)[2][8][4], int tid)
{
    const int lane = tid & 31, wid = tid >> 5;
    const int wm = wid >> 1, wn = wid & 1;
    const uint32_t s0 = sptr(sm);
    const int T = Ktot / 32;

    auto load = [&](int kt){
        uint32_t base = s0 + (kt % 3) * GST;
        int k0 = kt * 32;
#pragma unroll
        for (int i = 0; i < 2; i++){
            int e = tid + i*256;
            int r = e >> 2, c = e & 3;
            int gr = a_r0 + r; if (a_clamp) gr = (gr < a_clamp) ? gr : (a_clamp - 1);
            cpa16(base + r*80 + c*16, A + (size_t)gr*ldA + k0 + c*8);
        }
#pragma unroll
        for (int i = 0; i < 2; i++){
            int e = tid + i*256;
            int r = e >> 2, c = e & 3;
            cpa16(base + 10240 + r*80 + c*16, B + (size_t)(b_r0 + r)*ldB + k0 + c*8);
        }
        CP_COMMIT();
    };

    load(0);
    if (T > 1) load(1);
    for (int kt = 0; kt < T; kt++){
        if (kt + 1 < T) CP_WAIT1(); else CP_WAIT0();
        __syncthreads();
        if (kt + 2 < T) load(kt + 2);
        uint32_t aB = s0 + (kt % 3) * GST;
        uint32_t bB = aB + 10240;
#pragma unroll
        for (int kf = 0; kf < 2; kf++){
            uint32_t af[2][4], bf[8][2];
#pragma unroll
            for (int mt = 0; mt < 2; mt++){
                uint32_t a = aB + ((wm*32 + mt*16 + (lane & 15))*40 + kf*16 + (lane >> 4)*8)*2;
                ldm4(af[mt][0], af[mt][1], af[mt][2], af[mt][3], a);
            }
#pragma unroll
            for (int p = 0; p < 4; p++){
                uint32_t a = bB + ((wn*64 + p*16 + (lane & 7) + ((lane >> 4) & 1)*8)*40
                                   + kf*16 + ((lane >> 3) & 1)*8)*2;
                ldm4(bf[2*p][0], bf[2*p][1], bf[2*p+1][0], bf[2*p+1][1], a);
            }
#pragma unroll
            for (int mt = 0; mt < 2; mt++)
#pragma unroll
                for (int nf = 0; nf < 8; nf++)
                    mma16(acc[mt][nf], af[mt], bf[nf]);
        }
    }
    __syncthreads();
}

// ======================== kernels ========================
#define NX8 (MX*CC/8)
#define NW8 (CC*CC/8)
#define NCVT (NX8 + 4*NW8)

__global__ void __launch_bounds__(256) k_cvt_all(
    const float* __restrict__ x,  const float* __restrict__ wq,
    const float* __restrict__ wk, const float* __restrict__ wv,
    const float* __restrict__ wp)
{
    int i = blockIdx.x*256 + threadIdx.x;
    if (i >= NCVT) return;
    const float* s; __half* d; int off;
    if (i < NX8){ s = x; d = g_xh; off = i; }
    else {
        int j = i - NX8, w = j / NW8; off = j - w*NW8;
        s = (w == 0) ? wq : (w == 1) ? wk : (w == 2) ? wv : wp;
        d = (w == 0) ? g_wq : (w == 1) ? g_wk : (w == 2) ? g_wv : g_wp;
    }
    const float4* s4 = (const float4*)s;
    float4 a = s4[2*off], b = s4[2*off+1];
    uint4 o;
    o.x = packh2(a.x, a.y); o.y = packh2(a.z, a.w);
    o.z = packh2(b.x, b.y); o.w = packh2(b.z, b.w);
    ((uint4*)d)[off] = o;
}

// K1: QKV projection (NT), outputs [bh][tok][d] fp16. grid (6, 73, 3)
__global__ void __launch_bounds__(256) k_qkv(){
    extern __shared__ __align__(16) __half dsm[];
    int tid = threadIdx.x, lane = tid & 31, wid = tid >> 5;
    int wm = wid >> 1, wn = wid & 1, g = lane >> 2, t = lane & 3;
    int z = blockIdx.z, m0 = blockIdx.y*128, n0 = blockIdx.x*128;
    const __half* W = (z == 0) ? g_wq : (z == 1) ? g_wk : g_wv;
    __half* dst = (z == 0) ? g_q : (z == 1) ? g_k : g_v;
    float scale = (z == 0) ? SCALE : 1.f;

    float acc[2][8][4] = {};
    gemm_nt_h(g_xh, CC, m0, MX, W, CC, n0, CC, dsm, acc, tid);

#pragma unroll
    for (int mt = 0; mt < 2; mt++)
#pragma unroll
    for (int nf = 0; nf < 8; nf++){
        int col = n0 + wn*64 + nf*8 + t*2;
        int h = col >> 6, d = col & 63;
        int row0 = m0 + wm*32 + mt*16 + g;
#pragma unroll
        for (int rr = 0; rr < 2; rr++){
            int gm = row0 + rr*8;
            if (gm >= MX) continue;
            int b = gm / NN, n = gm - b*NN;
            uint32_t h2 = packh2(acc[mt][nf][rr*2]*scale, acc[mt][nf][rr*2+1]*scale);
            *(uint32_t*)&dst[(((size_t)(b*HH + h))*NP + n)*HD + d] = h2;
        }
    }
}

// ======================== flash attention core ========================
// 128 threads = 4 warps x 32 q-rows (2 M-frags per warp) -> half the LDSM
// traffic of the 8-warp version. Keys 0..575 = 9 full tiles; key 576 = tail.
#define QS 72
#define FST 18432
#define TAILB 73728
#define FL_SMEM (18432 + 3*FST + 256)   // 73984 B
#define TKV 9

template<bool FIRST>
__device__ __forceinline__ void flash_core(
    __half* smh, const __half* qg, const __half* kg, const __half* vg,
    float* __restrict__ mpl, int m0, int tid)
{
    const int lane = tid & 31, wid = tid >> 5;     // wid 0..3
    const int g = lane >> 2, t = lane & 3;
    const int wr = wid*32;
    const uint32_t s0 = sptr(smh);
    const uint32_t sq = s0;

    auto loadkv = [&](int kt){
        uint32_t base = s0 + 18432 + (kt % 3) * FST;
        int tok0 = kt * 64;
#pragma unroll
        for (int i = 0; i < 4; i++){
            int e = tid + i*128;
            int r = e >> 3, c = e & 7;
            cpa16(base + r*(QS*2) + c*16,        kg + (size_t)(tok0 + r)*HD + c*8);
            cpa16(base + 9216 + r*(QS*2) + c*16, vg + (size_t)(tok0 + r)*HD + c*8);
        }
        CP_COMMIT();
    };

    // q tile + tail rows (k576, v576) in group 0; first two K/V stages after
#pragma unroll
    for (int i = 0; i < 8; i++){
        int e = tid + i*128;
        int r = e >> 3, c = e & 7;
        cpa16(sq + r*(QS*2) + c*16, qg + (size_t)(m0 + r)*HD + c*8);
    }
    if (tid < 8)       cpa16(s0 + TAILB + tid*16,           kg + (size_t)(NN-1)*HD + tid*8);
    else if (tid < 16) cpa16(s0 + TAILB + 128 + (tid-8)*16, vg + (size_t)(NN-1)*HD + (tid-8)*8);
    CP_COMMIT();
    loadkv(0);
    loadkv(1);

    float mplv[2][2];
    if (!FIRST){
#pragma unroll
        for (int mt = 0; mt < 2; mt++){
            mplv[mt][0] = mpl[m0 + wr + mt*16 + g];
            mplv[mt][1] = mpl[m0 + wr + mt*16 + g + 8];
        }
    }

    asm volatile("cp.async.wait_group 2;\n" ::);   // q + tail ready
    __syncthreads();

    uint32_t qf[2][4][4];
#pragma unroll
    for (int mt = 0; mt < 2; mt++)
#pragma unroll
    for (int kf = 0; kf < 4; kf++){
        uint32_t a = sq + ((wr + mt*16 + (lane & 15))*QS + kf*16 + (lane >> 4)*8)*2;
        ldm4(qf[mt][kf][0], qf[mt][kf][1], qf[mt][kf][2], qf[mt][kf][3], a);
    }

    float mr[2][2], l[2][2];
    float ya[2][8][4];
#pragma unroll
    for (int mt = 0; mt < 2; mt++){
        mr[mt][0] = -1e30f; mr[mt][1] = -1e30f; l[mt][0] = 0.f; l[mt][1] = 0.f;
#pragma unroll
        for (int nf = 0; nf < 8; nf++){
            ya[mt][nf][0]=0; ya[mt][nf][1]=0; ya[mt][nf][2]=0; ya[mt][nf][3]=0;
        }
    }

    for (int kt = 0; kt < TKV; kt++){
        if (kt + 1 < TKV) CP_WAIT1(); else CP_WAIT0();
        __syncthreads();
        if (kt + 2 < TKV) loadkv(kt + 2);
        uint32_t sk = s0 + 18432 + (kt % 3) * FST;
        uint32_t sv = sk + 9216;

        // S = q @ k^T (K=64)
        float sa[2][8][4];
#pragma unroll
        for (int mt = 0; mt < 2; mt++)
#pragma unroll
        for (int nf = 0; nf < 8; nf++){
            sa[mt][nf][0]=0; sa[mt][nf][1]=0; sa[mt][nf][2]=0; sa[mt][nf][3]=0;
        }
#pragma unroll
        for (int kf = 0; kf < 4; kf++){
            uint32_t bf[8][2];
#pragma unroll
            for (int p = 0; p < 4; p++){
                uint32_t a = sk + ((p*16 + (lane & 7) + ((lane >> 4) & 1)*8)*QS
                                   + kf*16 + ((lane >> 3) & 1)*8)*2;
                ldm4(bf[2*p][0], bf[2*p][1], bf[2*p+1][0], bf[2*p+1][1], a);
            }
#pragma unroll
            for (int mt = 0; mt < 2; mt++)
#pragma unroll
            for (int nf = 0; nf < 8; nf++)
                mma16(sa[mt][nf], qf[mt][kf], bf[nf]);
        }

        uint32_t pf[2][4][4];
#pragma unroll
        for (int mt = 0; mt < 2; mt++){
            if (FIRST){
                float tm0 = -1e30f, tm1 = -1e30f;
#pragma unroll
                for (int nf = 0; nf < 8; nf++){
                    tm0 = fmaxf(tm0, fmaxf(sa[mt][nf][0], sa[mt][nf][1]));
                    tm1 = fmaxf(tm1, fmaxf(sa[mt][nf][2], sa[mt][nf][3]));
                }
                tm0 = fmaxf(tm0, __shfl_xor_sync(~0u, tm0, 1));
                tm0 = fmaxf(tm0, __shfl_xor_sync(~0u, tm0, 2));
                tm1 = fmaxf(tm1, __shfl_xor_sync(~0u, tm1, 1));
                tm1 = fmaxf(tm1, __shfl_xor_sync(~0u, tm1, 2));
                float mn0 = fmaxf(mr[mt][0], tm0), mn1 = fmaxf(mr[mt][1], tm1);
                float sc0 = __expf(mr[mt][0] - mn0), sc1 = __expf(mr[mt][1] - mn1);
                mr[mt][0] = mn0; mr[mt][1] = mn1;
                l[mt][0] *= sc0; l[mt][1] *= sc1;
#pragma unroll
                for (int nf = 0; nf < 8; nf++){
                    ya[mt][nf][0] *= sc0; ya[mt][nf][1] *= sc0;
                    ya[mt][nf][2] *= sc1; ya[mt][nf][3] *= sc1;
                }
                float rs0 = 0.f, rs1 = 0.f;
#pragma unroll
                for (int j = 0; j < 4; j++){
                    float p00 = __expf(sa[mt][2*j][0] - mn0),   p01 = __expf(sa[mt][2*j][1] - mn0);
                    float p02 = __expf(sa[mt][2*j][2] - mn1),   p03 = __expf(sa[mt][2*j][3] - mn1);
                    float p10 = __expf(sa[mt][2*j+1][0] - mn0), p11 = __expf(sa[mt][2*j+1][1] - mn0);
                    float p12 = __expf(sa[mt][2*j+1][2] - mn1), p13 = __expf(sa[mt][2*j+1][3] - mn1);
                    rs0 += p00 + p01 + p10 + p11;
                    rs1 += p02 + p03 + p12 + p13;
                    pf[mt][j][0] = packh2(p00, p01);
                    pf[mt][j][1] = packh2(p02, p03);
                    pf[mt][j][2] = packh2(p10, p11);
                    pf[mt][j][3] = packh2(p12, p13);
                }
                rs0 += __shfl_xor_sync(~0u, rs0, 1); rs0 += __shfl_xor_sync(~0u, rs0, 2);
                rs1 += __shfl_xor_sync(~0u, rs1, 1); rs1 += __shfl_xor_sync(~0u, rs1, 2);
                l[mt][0] += rs0; l[mt][1] += rs1;
            } else {
#pragma unroll
                for (int j = 0; j < 4; j++){
                    pf[mt][j][0] = packh2(__expf(sa[mt][2*j][0] - mplv[mt][0]),
                                          __expf(sa[mt][2*j][1] - mplv[mt][0]));
                    pf[mt][j][1] = packh2(__expf(sa[mt][2*j][2] - mplv[mt][1]),
                                          __expf(sa[mt][2*j][3] - mplv[mt][1]));
                    pf[mt][j][2] = packh2(__expf(sa[mt][2*j+1][0] - mplv[mt][0]),
                                          __expf(sa[mt][2*j+1][1] - mplv[mt][0]));
                    pf[mt][j][3] = packh2(__expf(sa[mt][2*j+1][2] - mplv[mt][1]),
                                          __expf(sa[mt][2*j+1][3] - mplv[mt][1]));
                }
            }
        }

        // Y += P @ V
#pragma unroll
        for (int kf = 0; kf < 4; kf++){
            uint32_t vf[8][2];
#pragma unroll
            for (int p = 0; p < 4; p++){
                uint32_t a = sv + ((kf*16 + (lane & 7) + ((lane >> 3) & 1)*8)*QS
                                   + p*16 + (lane >> 4)*8)*2;
                ldm4t(vf[2*p][0], vf[2*p][1], vf[2*p+1][0], vf[2*p+1][1], a);
            }
#pragma unroll
            for (int mt = 0; mt < 2; mt++)
#pragma unroll
            for (int nf = 0; nf < 8; nf++)
                mma16(ya[mt][nf], pf[mt][kf], vf[nf]);
        }
    }

    // ---- tail: key 576 (rank-1) ----
    {
        const __half2* kt2 = (const __half2*)(smh + TAILB/2);
        const __half2* vt2 = kt2 + 32;
#pragma unroll
        for (int mt = 0; mt < 2; mt++){
            float s0v = 0.f, s1v = 0.f;
#pragma unroll
            for (int kf = 0; kf < 4; kf++){
                float2 klo = __half22float2(kt2[kf*8 + t]);
                float2 khi = __half22float2(kt2[kf*8 + 4 + t]);
                float2 q0l = h2f(qf[mt][kf][0]), q1l = h2f(qf[mt][kf][1]);
                float2 q0h = h2f(qf[mt][kf][2]), q1h = h2f(qf[mt][kf][3]);
                s0v += q0l.x*klo.x + q0l.y*klo.y + q0h.x*khi.x + q0h.y*khi.y;
                s1v += q1l.x*klo.x + q1l.y*klo.y + q1h.x*khi.x + q1h.y*khi.y;
            }
            s0v += __shfl_xor_sync(~0u, s0v, 1); s0v += __shfl_xor_sync(~0u, s0v, 2);
            s1v += __shfl_xor_sync(~0u, s1v, 1); s1v += __shfl_xor_sync(~0u, s1v, 2);

            if (FIRST){
                float mn0 = fmaxf(mr[mt][0], s0v), mn1 = fmaxf(mr[mt][1], s1v);
                float sc0 = __expf(mr[mt][0] - mn0), sc1 = __expf(mr[mt][1] - mn1);
                float p0 = __expf(s0v - mn0), p1 = __expf(s1v - mn1);
                l[mt][0] = l[mt][0]*sc0 + p0; l[mt][1] = l[mt][1]*sc1 + p1;
#pragma unroll
                for (int nf = 0; nf < 8; nf++){
                    float2 v2 = __half22float2(vt2[nf*4 + t]);
                    ya[mt][nf][0] = ya[mt][nf][0]*sc0 + p0*v2.x;
                    ya[mt][nf][1] = ya[mt][nf][1]*sc0 + p0*v2.y;
                    ya[mt][nf][2] = ya[mt][nf][2]*sc1 + p1*v2.x;
                    ya[mt][nf][3] = ya[mt][nf][3]*sc1 + p1*v2.y;
                }
                if (t == 0){
                    mpl[m0 + wr + mt*16 + g]     = mn0 + __logf(l[mt][0]);
                    mpl[m0 + wr + mt*16 + g + 8] = mn1 + __logf(l[mt][1]);
                }
            } else {
                float p0 = __expf(s0v - mplv[mt][0]), p1 = __expf(s1v - mplv[mt][1]);
#pragma unroll
                for (int nf = 0; nf < 8; nf++){
                    float2 v2 = __half22float2(vt2[nf*4 + t]);
                    ya[mt][nf][0] += p0*v2.x; ya[mt][nf][1] += p0*v2.y;
                    ya[mt][nf][2] += p1*v2.x; ya[mt][nf][3] += p1*v2.y;
                }
            }
        }
    }
    __syncthreads();

    // normalize (FIRST only) and stage to smem fp32 [128][68]
    float* st = (float*)smh;
#pragma unroll
    for (int mt = 0; mt < 2; mt++){
        float inv0 = FIRST ? (1.f / l[mt][0]) : 1.f;
        float inv1 = FIRST ? (1.f / l[mt][1]) : 1.f;
#pragma unroll
        for (int nf = 0; nf < 8; nf++){
            int d = nf*8 + t*2;
            st[(wr + mt*16 + g)*68 + d]         = ya[mt][nf][0]*inv0;
            st[(wr + mt*16 + g)*68 + d + 1]     = ya[mt][nf][1]*inv0;
            st[(wr + mt*16 + g + 8)*68 + d]     = ya[mt][nf][2]*inv1;
            st[(wr + mt*16 + g + 8)*68 + d + 1] = ya[mt][nf][3]*inv1;
        }
    }
    __syncthreads();
}

// K2: Y = softmax(qk) @ v -> g_Yh + g_Yf + g_mpl. grid (5, 192), 128 threads
__global__ void __launch_bounds__(128) k_av_f(){
    extern __shared__ __align__(16) __half dsm[];
    int tid = threadIdx.x;
    int m0 = blockIdx.x*128, bh = blockIdx.y;
    size_t ob = (size_t)bh*NP*HD;
    flash_core<true>(dsm, g_q + ob, g_k + ob, g_v + ob, g_mpl + (size_t)bh*NP, m0, tid);

    const float* src = (const float*)dsm + tid*68;
    size_t o = ob + (size_t)(m0 + tid)*HD;
#pragma unroll
    for (int i = 0; i < 16; i++)
        ((float4*)(g_Yf + o))[i] = ((const float4*)src)[i];
#pragma unroll
    for (int i = 0; i < 8; i++){
        uint4 u;
        u.x = packh2(src[i*8+0], src[i*8+1]);
        u.y = packh2(src[i*8+2], src[i*8+3]);
        u.z = packh2(src[i*8+4], src[i*8+5]);
        u.w = packh2(src[i*8+6], src[i*8+7]);
        ((uint4*)(g_Yh + o))[i] = u;
    }
}

// K3: Z = softmax(qk) @ Y; hb = (1-2b)Y + 3b*Z. grid (5, 192), 128 threads
__global__ void __launch_bounds__(128) k_ay_f(const float* __restrict__ lamb){
    extern __shared__ __align__(16) __half dsm[];
    int tid = threadIdx.x;
    int m0 = blockIdx.x*128, bh = blockIdx.y;
    int b = bh / HH, h = bh - b*HH;
    size_t ob = (size_t)bh*NP*HD;
    flash_core<false>(dsm, g_q + ob, g_k + ob, g_Yh + ob, g_mpl + (size_t)bh*NP, m0, tid);

    float beta = lamb[h];
    float c0 = 1.f - 2.f*beta, c1 = 3.f*beta;
    int tok = m0 + tid;
    if (tok < NN){
        const float* zs = (const float*)dsm + tid*68;
        const float* yf = g_Yf + ob + (size_t)tok*HD;
        __half* dst = g_hb + ((size_t)(b*NN + tok))*CC + h*64;
#pragma unroll
        for (int i = 0; i < 8; i++){
            uint4 u;
            u.x = packh2(c0*yf[i*8+0] + c1*zs[i*8+0], c0*yf[i*8+1] + c1*zs[i*8+1]);
            u.y = packh2(c0*yf[i*8+2] + c1*zs[i*8+2], c0*yf[i*8+3] + c1*zs[i*8+3]);
            u.z = packh2(c0*yf[i*8+4] + c1*zs[i*8+4], c0*yf[i*8+5] + c1*zs[i*8+5]);
            u.w = packh2(c0*yf[i*8+6] + c1*zs[i*8+6], c0*yf[i*8+7] + c1*zs[i*8+7]);
            ((uint4*)dst)[i] = u;
        }
    }
}

// K4: out = hb @ Wp^T + bp (NT, fp32 out). grid (6, 73)
__global__ void __launch_bounds__(256)
k_proj(const float* __restrict__ bp, float* __restrict__ out){
    extern __shared__ __align__(16) __half dsm[];
    int tid = threadIdx.x, lane = tid & 31, wid = tid >> 5;
    int wm = wid >> 1, wn = wid & 1, g = lane >> 2, t = lane & 3;
    int m0 = blockIdx.y*128, n0 = blockIdx.x*128;

    float acc[2][8][4] = {};
    gemm_nt_h(g_hb, CC, m0, MX, g_wp, CC, n0, CC, dsm, acc, tid);

#pragma unroll
    for (int mt = 0; mt < 2; mt++)
#pragma unroll
    for (int nf = 0; nf < 8; nf++){
        int col = n0 + wn*64 + nf*8 + t*2;
        float b0 = bp[col], b1 = bp[col + 1];
        int row0 = m0 + wm*32 + mt*16 + g;
#pragma unroll
        for (int rr = 0; rr < 2; rr++){
            int gm = row0 + rr*8;
            if (gm >= MX) continue;
            *(float2*)&out[(size_t)gm*CC + col] =
                make_float2(acc[mt][nf][rr*2] + b0, acc[mt][nf][rr*2+1] + b1);
        }
    }
}

// ======================== host launcher ========================
extern "C" void kernel_launch(void* const* d_in, const int* in_sizes, int n_in,
                              void* d_out, int out_size)
{
    const float* x    = (const float*)d_in[0];
    const float* Wq   = (const float*)d_in[1];
    const float* Wk   = (const float*)d_in[2];
    const float* Wv   = (const float*)d_in[3];
    const float* Wp   = (const float*)d_in[4];
    const float* bp   = (const float*)d_in[5];
    const float* lamb = (const float*)d_in[6];
    float* out = (float*)d_out;

    static bool attr_done = false;
    if (!attr_done){
        cudaFuncSetAttribute(k_qkv,  cudaFuncAttributeMaxDynamicSharedMemorySize, GEMM_SMEM);
        cudaFuncSetAttribute(k_proj, cudaFuncAttributeMaxDynamicSharedMemorySize, GEMM_SMEM);
        cudaFuncSetAttribute(k_av_f, cudaFuncAttributeMaxDynamicSharedMemorySize, FL_SMEM);
        cudaFuncSetAttribute(k_ay_f, cudaFuncAttributeMaxDynamicSharedMemorySize, FL_SMEM);
        attr_done = true;
    }

    k_cvt_all<<<(NCVT + 255)/256, 256>>>(x, Wq, Wk, Wv, Wp);
    k_qkv <<<dim3(CC/128, (MX + 127)/128, 3), 256, GEMM_SMEM>>>();
    k_av_f<<<dim3(NP/128, BH), 128, FL_SMEM>>>();
    k_ay_f<<<dim3(NP/128, BH), 128, FL_SMEM>>>(lamb);
    k_proj<<<dim3(CC/128, (MX + 127)/128), 256, GEMM_SMEM>>>(bp, out);
}